// round 12
// baseline (speedup 1.0000x reference)
#include <cuda_runtime.h>
#include <cuda_fp16.h>
#include <cstdint>

#define L  2
#define T  128
#define NB 64      // batch N
#define H  512
#define E  256
#define A  200
#define V  1000
#define S  40
#define LT (L*T)   // 256

// ---------------- scratch (device globals) ----------------
__device__ __align__(16) __half g_KprojH[L*T*NB*A];  // (l,t,n,a) fp16
__device__ __align__(16) __half g_eoH[L*T*NB*H];     // fp16 copy of eo
__device__ __align__(16) __half g_qprojH[L*NB*A];    // (l,n,a) fp16
__device__ __align__(16) __half g_xH[(E+H)*NB];      // (k,n) fp16 GRU0 input
__device__ __align__(16) float g_h[2][L][H*NB];      // fp32 recurrent state (k,n)
__device__ __align__(16) __half g_hH[2][L][H*NB];    // fp16 operand copy
__device__ __align__(16) __half g_projH[H*NB];       // (k,n) fp16
__device__ unsigned g_bar_count;
__device__ volatile unsigned g_bar_gen;

// ---------------- helpers ----------------
__device__ __forceinline__ float4 ld_half4(const __half* __restrict__ p) {
    uint2 u = *reinterpret_cast<const uint2*>(p);
    __half2 h0 = *reinterpret_cast<const __half2*>(&u.x);
    __half2 h1 = *reinterpret_cast<const __half2*>(&u.y);
    float2 f0 = __half22float2(h0), f1 = __half22float2(h1);
    return make_float4(f0.x, f0.y, f1.x, f1.y);
}

__device__ __forceinline__ float fast_rcp(float q) {
    float r = __uint_as_float(0x7EF311C3u - __float_as_uint(q));
    r = r * (2.0f - q * r);
    r = r * (2.0f - q * r);
    r = r * (2.0f - q * r);
    return r;
}

__device__ __forceinline__ float tanh_fast(float x) {
    const float c = 7.99881172180175781f;
    x = fminf(fmaxf(x, -c), c);
    float x2 = x * x;
    float p = fmaf(x2, -2.76076847742355e-16f, 2.00018790482477e-13f);
    p = fmaf(x2, p, -8.60467152213735e-11f);
    p = fmaf(x2, p,  5.12229709037114e-08f);
    p = fmaf(x2, p,  1.48572235717979e-05f);
    p = fmaf(x2, p,  6.37261928875436e-04f);
    p = fmaf(x2, p,  4.89352455891786e-03f);
    p = p * x;
    float q = fmaf(x2, 1.19825839466702e-06f, 1.18534705686654e-04f);
    q = fmaf(x2, q, 2.26843463243900e-03f);
    q = fmaf(x2, q, 4.89352518554385e-03f);
    return p * fast_rcp(q);
}

__device__ __forceinline__ float sigmoid_fast(float x) {
    return fmaf(tanh_fast(0.5f * x), 0.5f, 0.5f);
}

__device__ __forceinline__ void grid_sync(int nb) {
    __syncthreads();
    if (threadIdx.x == 0) {
        __threadfence();
        unsigned gen = g_bar_gen;
        if (atomicAdd(&g_bar_count, 1u) == (unsigned)nb - 1u) {
            g_bar_count = 0u;
            __threadfence();
            g_bar_gen = gen + 1u;
        } else {
            while (g_bar_gen == gen) { __nanosleep(64); }
        }
        __threadfence();
    }
    __syncthreads();
}

// ---------------- prep kernels (once per launch) ----------------
__global__ void prep_hinit(const float* __restrict__ efs) {
    int i = blockIdx.x * 256 + threadIdx.x;        // over L*NB*H
    if (i >= L * NB * H) return;
    int k = i % H;
    int n = (i / H) % NB;
    int l = i / (NB * H);
    float v = efs[i];
    g_h[0][l][k * NB + n] = v;
    g_hH[0][l][k * NB + n] = __float2half(v);
}

__global__ void eo_to_half(const float* __restrict__ eo) {
    int i = blockIdx.x * 256 + threadIdx.x;        // over L*T*NB*H/2
    if (i >= L * T * NB * H / 2) return;
    float2 v = reinterpret_cast<const float2*>(eo)[i];
    reinterpret_cast<__half2*>(g_eoH)[i] = __floats2half2_rn(v.x, v.y);
}

__global__ void kproj_gemm(const float* __restrict__ eo,
                           const float* __restrict__ Kw,
                           const float* __restrict__ Kb) {
    const int l   = blockIdx.z;
    const int tn0 = blockIdx.x * 64;
    const int a0  = blockIdx.y * 64;
    const float* Ab = eo + (size_t)l * (T * NB) * H;
    const float* Bb = Kw + (size_t)l * A * H;
    __shared__ float As[16][64];
    __shared__ float Bs[16][64];
    const int tid = threadIdx.x;
    const int tr = tid >> 4, tc = tid & 15;
    const int lr = tid >> 2;
    const int lk = (tid & 3) * 4;
    float acc[4][4];
    #pragma unroll
    for (int i = 0; i < 4; i++)
        #pragma unroll
        for (int j = 0; j < 4; j++) acc[i][j] = 0.0f;

    for (int k0 = 0; k0 < H; k0 += 16) {
        float4 a4 = *reinterpret_cast<const float4*>(&Ab[(size_t)(tn0 + lr) * H + k0 + lk]);
        As[lk + 0][lr] = a4.x; As[lk + 1][lr] = a4.y;
        As[lk + 2][lr] = a4.z; As[lk + 3][lr] = a4.w;
        float4 b4 = make_float4(0.f, 0.f, 0.f, 0.f);
        if (a0 + lr < A)
            b4 = *reinterpret_cast<const float4*>(&Bb[(size_t)(a0 + lr) * H + k0 + lk]);
        Bs[lk + 0][lr] = b4.x; Bs[lk + 1][lr] = b4.y;
        Bs[lk + 2][lr] = b4.z; Bs[lk + 3][lr] = b4.w;
        __syncthreads();
        #pragma unroll
        for (int kk = 0; kk < 16; kk++) {
            float4 av = *reinterpret_cast<const float4*>(&As[kk][tr * 4]);
            float4 bv = *reinterpret_cast<const float4*>(&Bs[kk][tc * 4]);
            acc[0][0]=fmaf(av.x,bv.x,acc[0][0]); acc[0][1]=fmaf(av.x,bv.y,acc[0][1]);
            acc[0][2]=fmaf(av.x,bv.z,acc[0][2]); acc[0][3]=fmaf(av.x,bv.w,acc[0][3]);
            acc[1][0]=fmaf(av.y,bv.x,acc[1][0]); acc[1][1]=fmaf(av.y,bv.y,acc[1][1]);
            acc[1][2]=fmaf(av.y,bv.z,acc[1][2]); acc[1][3]=fmaf(av.y,bv.w,acc[1][3]);
            acc[2][0]=fmaf(av.z,bv.x,acc[2][0]); acc[2][1]=fmaf(av.z,bv.y,acc[2][1]);
            acc[2][2]=fmaf(av.z,bv.z,acc[2][2]); acc[2][3]=fmaf(av.z,bv.w,acc[2][3]);
            acc[3][0]=fmaf(av.w,bv.x,acc[3][0]); acc[3][1]=fmaf(av.w,bv.y,acc[3][1]);
            acc[3][2]=fmaf(av.w,bv.z,acc[3][2]); acc[3][3]=fmaf(av.w,bv.w,acc[3][3]);
        }
        __syncthreads();
    }
    #pragma unroll
    for (int i = 0; i < 4; i++) {
        int tn = tn0 + tr * 4 + i;
        #pragma unroll
        for (int j = 0; j < 4; j++) {
            int a = a0 + tc * 4 + j;
            if (a < A)
                g_KprojH[(size_t)(l * T * NB + tn) * A + a] =
                    __float2half(acc[i][j] + Kb[l * A + a]);
        }
    }
}

// ============ phase bodies (device functions over task indices) ============

// qproj, 4 a-rows per task; 100 tasks (l = t/50, a0 = (t%50)*4)
__device__ __forceinline__ void ph_qproj4(int t, const float* __restrict__ Qw,
                                          const float* __restrict__ Qb,
                                          int cur, char* sraw) {
    float (*sw)[2][4][16] = reinterpret_cast<float(*)[2][4][16]>(sraw);      // 4KB
    float (*sacc)[16][64] = reinterpret_cast<float(*)[16][64]>(sraw + 4096); // 16KB
    const int l = t / 50, a0 = (t % 50) * 4;
    const int tid = threadIdx.x;
    const int w = tid >> 5, lane = tid & 31;
    const int half = lane >> 4, ln = lane & 15;
    const int n0 = ln * 4;
    const __half* __restrict__ xin = g_hH[cur][l];
    const float* __restrict__ wbase = Qw + ((size_t)(l * A + a0)) * H;

    float acc[4][4] = {};
    const int kb = w * 64 + half * 32;
    #pragma unroll
    for (int kc = 0; kc < 32; kc += 16) {
        int k0 = kb + kc;
        #pragma unroll
        for (int r = 0; r < 4; r++)
            sw[w][half][r][ln] = wbase[(size_t)r * H + k0 + ln];
        __syncwarp();
        #pragma unroll
        for (int c = 0; c < 16; c++) {
            float4 xv = ld_half4(&xin[(k0 + c) * NB + n0]);
            #pragma unroll
            for (int r = 0; r < 4; r++) {
                float wv = sw[w][half][r][c];
                acc[r][0] = fmaf(wv, xv.x, acc[r][0]);
                acc[r][1] = fmaf(wv, xv.y, acc[r][1]);
                acc[r][2] = fmaf(wv, xv.z, acc[r][2]);
                acc[r][3] = fmaf(wv, xv.w, acc[r][3]);
            }
        }
        __syncwarp();
    }
    const int ws = w * 2 + half;
    #pragma unroll
    for (int r = 0; r < 4; r++)
        *(float4*)&sacc[r][ws][n0] = make_float4(acc[r][0], acc[r][1], acc[r][2], acc[r][3]);
    __syncthreads();
    {
        int r = tid >> 6, n = tid & 63;
        float s = 0.f;
        #pragma unroll
        for (int ws2 = 0; ws2 < 16; ws2++) s += sacc[r][ws2][n];
        g_qprojH[((size_t)l * NB + n) * A + a0 + r] = __float2half(s + Qb[l * A + a0 + r]);
    }
    __syncthreads();
}

// attention: scores + softmax + context + embedding; task = n (64 tasks)
__device__ __forceinline__ void ph_attn(int n, const float* __restrict__ Vw,
                                        const float* __restrict__ Vb,
                                        const float* __restrict__ embW,
                                        const int* __restrict__ targets,
                                        int s, char* sraw) {
    float* sc  = reinterpret_cast<float*>(sraw);       // 256
    float* wgt = sc + LT;                              // 256
    float* red = wgt + LT;                             // 8
    const int tid = threadIdx.x;
    const int w = tid >> 5, lane = tid & 31;

    // scores: warp w covers lt = w*32 .. w*32+31
    for (int i = 0; i < 32; i++) {
        int lt = w * 32 + i;
        int l = lt >> 7;
        const __half* kp = g_KprojH + (size_t)(lt * NB + n) * A;
        const __half* qp = g_qprojH + (size_t)(l * NB + n) * A;
        const float* vw = Vw + l * A;
        float acc = 0.f;
        #pragma unroll
        for (int jj = 0; jj < 4; jj++) {
            int a = jj * 64 + lane * 2;
            if (a < A) {
                float2 v = *(const float2*)&vw[a];
                float2 k = __half22float2(*(const __half2*)&kp[a]);
                float2 q = __half22float2(*(const __half2*)&qp[a]);
                acc = fmaf(v.x, tanh_fast(q.x + k.x), acc);
                acc = fmaf(v.y, tanh_fast(q.y + k.y), acc);
            }
        }
        #pragma unroll
        for (int o = 16; o > 0; o >>= 1)
            acc += __shfl_down_sync(0xFFFFFFFFu, acc, o);
        if (lane == 0) sc[lt] = acc + Vb[l];
    }
    __syncthreads();

    // softmax over 256
    float v0 = sc[tid];
    float m = v0;
    #pragma unroll
    for (int o = 16; o > 0; o >>= 1)
        m = fmaxf(m, __shfl_xor_sync(0xFFFFFFFFu, m, o));
    if (lane == 0) red[tid >> 5] = m;
    __syncthreads();
    if (tid < 8) {
        float v = red[tid];
        #pragma unroll
        for (int o = 4; o > 0; o >>= 1)
            v = fmaxf(v, __shfl_xor_sync(0xFFu, v, o, 8));
        if (tid == 0) red[0] = v;
    }
    __syncthreads();
    float mx = red[0];
    float e = __expf(v0 - mx);
    float su = e;
    #pragma unroll
    for (int o = 16; o > 0; o >>= 1)
        su += __shfl_xor_sync(0xFFFFFFFFu, su, o);
    __syncthreads();
    if (lane == 0) red[tid >> 5] = su;
    __syncthreads();
    if (tid < 8) {
        float v = red[tid];
        #pragma unroll
        for (int o = 4; o > 0; o >>= 1)
            v += __shfl_xor_sync(0xFFu, v, o, 8);
        if (tid == 0) red[0] = v;
    }
    __syncthreads();
    wgt[tid] = e * (1.0f / red[0]);
    __syncthreads();

    // context: thread owns h-pair (2*tid, 2*tid+1)
    const __half2* ep = reinterpret_cast<const __half2*>(g_eoH + (size_t)n * H) + tid;
    float ax = 0.f, ay = 0.f;
    #pragma unroll 16
    for (int lt = 0; lt < LT; lt++) {
        float2 f = __half22float2(ep[(size_t)lt * (NB * H / 2)]);
        float wv = wgt[lt];
        ax = fmaf(wv, f.x, ax);
        ay = fmaf(wv, f.y, ay);
    }
    g_xH[(E + 2 * tid + 0) * NB + n] = __float2half(ax);
    g_xH[(E + 2 * tid + 1) * NB + n] = __float2half(ay);

    int tok = (s == 0) ? 1 : targets[n * S + (s - 1)];
    g_xH[tid * NB + n] = __float2half(fmaxf(embW[(size_t)tok * E + tid], 0.0f));
    __syncthreads();
}

// GRU: 2 j rows per task; 256 tasks
template <int KIN>
__device__ __forceinline__ void ph_gru(int t, const float* __restrict__ Wih,
                                       const float* __restrict__ Whh,
                                       const float* __restrict__ bih,
                                       const float* __restrict__ bhh,
                                       int cur, int layer, char* sraw) {
    float (*sw)[2][6][16]    = reinterpret_cast<float(*)[2][6][16]>(sraw);            // 6KB
    float (*sacc)[4][16][64] = reinterpret_cast<float(*)[4][16][64]>(sraw + 6144);    // 32KB
    float (*sgate)[4][64]    = reinterpret_cast<float(*)[4][64]>(sraw + 6144 + 32768);// 2KB
    const int j0 = t * 2;
    const int tid = threadIdx.x;
    const int w = tid >> 5, lane = tid & 31;
    const int half = lane >> 4, ln = lane & 15;
    const int n0 = ln * 4;
    const int nxt = cur ^ 1;

    const __half* __restrict__ xin = (layer == 0) ? g_xH : g_hH[nxt][0];
    const __half* __restrict__ hin = g_hH[cur][layer];
    const float* __restrict__ hprev = g_h[cur][layer];
    float* __restrict__ hout = g_h[nxt][layer];
    __half* __restrict__ houtH = g_hH[nxt][layer];

    float aR[2][4] = {}, aZ[2][4] = {}, aI[2][4] = {}, aH[2][4] = {};

    // x part
    {
        const int kx = KIN / 8;
        const int kb = w * kx + half * (kx / 2);
        #pragma unroll
        for (int kc = 0; kc < kx / 2; kc += 16) {
            int k0 = kb + kc;
            #pragma unroll
            for (int g = 0; g < 6; g++) {
                int jj = g >= 3 ? 1 : 0;
                int gate = g - jj * 3;
                sw[w][half][g][ln] = Wih[((size_t)gate * H + j0 + jj) * KIN + k0 + ln];
            }
            __syncwarp();
            #pragma unroll
            for (int c = 0; c < 16; c++) {
                float4 xv = ld_half4(&xin[(k0 + c) * NB + n0]);
                #pragma unroll
                for (int jj = 0; jj < 2; jj++) {
                    float wR = sw[w][half][jj * 3 + 0][c];
                    float wZ = sw[w][half][jj * 3 + 1][c];
                    float wN = sw[w][half][jj * 3 + 2][c];
                    aR[jj][0]=fmaf(wR,xv.x,aR[jj][0]); aR[jj][1]=fmaf(wR,xv.y,aR[jj][1]);
                    aR[jj][2]=fmaf(wR,xv.z,aR[jj][2]); aR[jj][3]=fmaf(wR,xv.w,aR[jj][3]);
                    aZ[jj][0]=fmaf(wZ,xv.x,aZ[jj][0]); aZ[jj][1]=fmaf(wZ,xv.y,aZ[jj][1]);
                    aZ[jj][2]=fmaf(wZ,xv.z,aZ[jj][2]); aZ[jj][3]=fmaf(wZ,xv.w,aZ[jj][3]);
                    aI[jj][0]=fmaf(wN,xv.x,aI[jj][0]); aI[jj][1]=fmaf(wN,xv.y,aI[jj][1]);
                    aI[jj][2]=fmaf(wN,xv.z,aI[jj][2]); aI[jj][3]=fmaf(wN,xv.w,aI[jj][3]);
                }
            }
            __syncwarp();
        }
    }
    // h part
    {
        const int kb = w * 64 + half * 32;
        #pragma unroll
        for (int kc = 0; kc < 32; kc += 16) {
            int k0 = kb + kc;
            #pragma unroll
            for (int g = 0; g < 6; g++) {
                int jj = g >= 3 ? 1 : 0;
                int gate = g - jj * 3;
                sw[w][half][g][ln] = Whh[((size_t)gate * H + j0 + jj) * H + k0 + ln];
            }
            __syncwarp();
            #pragma unroll
            for (int c = 0; c < 16; c++) {
                float4 xv = ld_half4(&hin[(k0 + c) * NB + n0]);
                #pragma unroll
                for (int jj = 0; jj < 2; jj++) {
                    float wR = sw[w][half][jj * 3 + 0][c];
                    float wZ = sw[w][half][jj * 3 + 1][c];
                    float wN = sw[w][half][jj * 3 + 2][c];
                    aR[jj][0]=fmaf(wR,xv.x,aR[jj][0]); aR[jj][1]=fmaf(wR,xv.y,aR[jj][1]);
                    aR[jj][2]=fmaf(wR,xv.z,aR[jj][2]); aR[jj][3]=fmaf(wR,xv.w,aR[jj][3]);
                    aZ[jj][0]=fmaf(wZ,xv.x,aZ[jj][0]); aZ[jj][1]=fmaf(wZ,xv.y,aZ[jj][1]);
                    aZ[jj][2]=fmaf(wZ,xv.z,aZ[jj][2]); aZ[jj][3]=fmaf(wZ,xv.w,aZ[jj][3]);
                    aH[jj][0]=fmaf(wN,xv.x,aH[jj][0]); aH[jj][1]=fmaf(wN,xv.y,aH[jj][1]);
                    aH[jj][2]=fmaf(wN,xv.z,aH[jj][2]); aH[jj][3]=fmaf(wN,xv.w,aH[jj][3]);
                }
            }
            __syncwarp();
        }
    }
    const int ws = w * 2 + half;
    #pragma unroll
    for (int jj = 0; jj < 2; jj++) {
        *(float4*)&sacc[jj][0][ws][n0] = make_float4(aR[jj][0], aR[jj][1], aR[jj][2], aR[jj][3]);
        *(float4*)&sacc[jj][1][ws][n0] = make_float4(aZ[jj][0], aZ[jj][1], aZ[jj][2], aZ[jj][3]);
        *(float4*)&sacc[jj][2][ws][n0] = make_float4(aI[jj][0], aI[jj][1], aI[jj][2], aI[jj][3]);
        *(float4*)&sacc[jj][3][ws][n0] = make_float4(aH[jj][0], aH[jj][1], aH[jj][2], aH[jj][3]);
    }
    __syncthreads();
    #pragma unroll
    for (int i = 0; i < 2; i++) {
        int idx = tid + 256 * i;
        int jj = idx >> 8;
        int g  = (idx >> 6) & 3;
        int n  = idx & 63;
        float ssum = 0.f;
        #pragma unroll
        for (int ws2 = 0; ws2 < 16; ws2++) ssum += sacc[jj][g][ws2][n];
        sgate[jj][g][n] = ssum;
    }
    __syncthreads();
    if (tid < 128) {
        int jj = tid >> 6, n = tid & 63;
        int j = j0 + jj;
        float r = sigmoid_fast(sgate[jj][0][n] + bih[j] + bhh[j]);
        float z = sigmoid_fast(sgate[jj][1][n] + bih[H + j] + bhh[H + j]);
        float nn = tanh_fast(sgate[jj][2][n] + bih[2 * H + j] +
                             r * (sgate[jj][3][n] + bhh[2 * H + j]));
        float hp = hprev[j * NB + n];
        float hv = fmaf(z, hp - nn, nn);
        hout[j * NB + n] = hv;
        houtH[j * NB + n] = __float2half(hv);
    }
    __syncthreads();
}

// proj: 4 j rows per task; 128 tasks. nxt = index of h written this step.
__device__ __forceinline__ void ph_proj4(int t, const float* __restrict__ Pw0,
                                         const float* __restrict__ Pb0,
                                         int nxt, char* sraw) {
    float (*sw)[2][4][16] = reinterpret_cast<float(*)[2][4][16]>(sraw);
    float (*sacc)[16][64] = reinterpret_cast<float(*)[16][64]>(sraw + 4096);
    const int j0 = t * 4;
    const int tid = threadIdx.x;
    const int w = tid >> 5, lane = tid & 31;
    const int half = lane >> 4, ln = lane & 15;
    const int n0 = ln * 4;
    const __half* __restrict__ xin = g_hH[nxt][1];
    const float* __restrict__ wbase = Pw0 + (size_t)j0 * H;

    float acc[4][4] = {};
    const int kb = w * 64 + half * 32;
    #pragma unroll
    for (int kc = 0; kc < 32; kc += 16) {
        int k0 = kb + kc;
        #pragma unroll
        for (int r = 0; r < 4; r++)
            sw[w][half][r][ln] = wbase[(size_t)r * H + k0 + ln];
        __syncwarp();
        #pragma unroll
        for (int c = 0; c < 16; c++) {
            float4 xv = ld_half4(&xin[(k0 + c) * NB + n0]);
            #pragma unroll
            for (int r = 0; r < 4; r++) {
                float wv = sw[w][half][r][c];
                acc[r][0] = fmaf(wv, xv.x, acc[r][0]);
                acc[r][1] = fmaf(wv, xv.y, acc[r][1]);
                acc[r][2] = fmaf(wv, xv.z, acc[r][2]);
                acc[r][3] = fmaf(wv, xv.w, acc[r][3]);
            }
        }
        __syncwarp();
    }
    const int ws = w * 2 + half;
    #pragma unroll
    for (int r = 0; r < 4; r++)
        *(float4*)&sacc[r][ws][n0] = make_float4(acc[r][0], acc[r][1], acc[r][2], acc[r][3]);
    __syncthreads();
    {
        int r = tid >> 6, n = tid & 63;
        float s = 0.f;
        #pragma unroll
        for (int ws2 = 0; ws2 < 16; ws2++) s += sacc[r][ws2][n];
        g_projH[(j0 + r) * NB + n] = __float2half(fmaxf(s + Pb0[j0 + r], 0.f));
    }
    __syncthreads();
}

// logits: 8 v rows per task; 125 tasks.
__device__ __forceinline__ void ph_logits8(int t, const float* __restrict__ Pw1,
                                           const float* __restrict__ Pb1,
                                           float* __restrict__ out, int s, char* sraw) {
    float (*sw)[2][8][16] = reinterpret_cast<float(*)[2][8][16]>(sraw);          // 8KB
    float (*sacc)[16][64] = reinterpret_cast<float(*)[16][64]>(sraw + 8192);     // 32KB
    const int v0 = t * 8;
    const int tid = threadIdx.x;
    const int w = tid >> 5, lane = tid & 31;
    const int half = lane >> 4, ln = lane & 15;
    const int n0 = ln * 4;
    const float* __restrict__ wbase = Pw1 + (size_t)v0 * H;

    float acc[8][4] = {};
    const int kb = w * 64 + half * 32;
    #pragma unroll
    for (int kc = 0; kc < 32; kc += 16) {
        int k0 = kb + kc;
        #pragma unroll
        for (int r = 0; r < 8; r++)
            sw[w][half][r][ln] = wbase[(size_t)r * H + k0 + ln];
        __syncwarp();
        #pragma unroll
        for (int c = 0; c < 16; c++) {
            float4 xv = ld_half4(&g_projH[(k0 + c) * NB + n0]);
            #pragma unroll
            for (int r = 0; r < 8; r++) {
                float wv = sw[w][half][r][c];
                acc[r][0] = fmaf(wv, xv.x, acc[r][0]);
                acc[r][1] = fmaf(wv, xv.y, acc[r][1]);
                acc[r][2] = fmaf(wv, xv.z, acc[r][2]);
                acc[r][3] = fmaf(wv, xv.w, acc[r][3]);
            }
        }
        __syncwarp();
    }
    const int ws = w * 2 + half;
    #pragma unroll
    for (int r = 0; r < 8; r++)
        *(float4*)&sacc[r][ws][n0] = make_float4(acc[r][0], acc[r][1], acc[r][2], acc[r][3]);
    __syncthreads();
    #pragma unroll
    for (int i = 0; i < 2; i++) {
        int idx = tid + 256 * i;
        int r = idx >> 6, n = idx & 63;
        float s2 = 0.f;
        #pragma unroll
        for (int ws2 = 0; ws2 < 16; ws2++) s2 += sacc[r][ws2][n];
        out[((size_t)n * S + s) * V + v0 + r] = s2 + Pb1[v0 + r];
    }
    __syncthreads();
}

// ---------------- the persistent decode kernel ----------------
__global__ void __launch_bounds__(256, 2)
decode_persist(const int* __restrict__ targets, const float* __restrict__ embW,
               const float* __restrict__ Qw, const float* __restrict__ Qb,
               const float* __restrict__ Vw, const float* __restrict__ Vb,
               const float* __restrict__ Wih0, const float* __restrict__ Whh0,
               const float* __restrict__ bih0, const float* __restrict__ bhh0,
               const float* __restrict__ Wih1, const float* __restrict__ Whh1,
               const float* __restrict__ bih1, const float* __restrict__ bhh1,
               const float* __restrict__ Pw0, const float* __restrict__ Pb0,
               const float* __restrict__ Pw1, const float* __restrict__ Pb1,
               float* __restrict__ out)
{
    __shared__ __align__(16) char sraw[40960];
    const int nb = gridDim.x;

    // prologue: qproj(0), attn(0)
    for (int t = blockIdx.x; t < 100; t += nb) ph_qproj4(t, Qw, Qb, 0, sraw);
    grid_sync(nb);
    for (int t = blockIdx.x; t < NB; t += nb) ph_attn(t, Vw, Vb, embW, targets, 0, sraw);
    grid_sync(nb);

    for (int s = 0; s < S; s++) {
        const int cur = s & 1;
        const int nxt = cur ^ 1;

        // C: gru layer 0
        for (int t = blockIdx.x; t < 256; t += nb)
            ph_gru<E + H>(t, Wih0, Whh0, bih0, bhh0, cur, 0, sraw);
        grid_sync(nb);

        // D: gru layer 1
        for (int t = blockIdx.x; t < 256; t += nb)
            ph_gru<H>(t, Wih1, Whh1, bih1, bhh1, cur, 1, sraw);
        grid_sync(nb);

        // E: proj(s) [0..127] + qproj(s+1) [128..227]
        {
            int nt = (s < S - 1) ? 228 : 128;
            for (int t = blockIdx.x; t < nt; t += nb) {
                if (t < 128) ph_proj4(t, Pw0, Pb0, nxt, sraw);
                else         ph_qproj4(t - 128, Qw, Qb, nxt, sraw);
            }
        }
        grid_sync(nb);

        // F: logits(s) [0..124] + attn(s+1) [125..188]
        {
            int nt = (s < S - 1) ? 189 : 125;
            for (int t = blockIdx.x; t < nt; t += nb) {
                if (t < 125) ph_logits8(t, Pw1, Pb1, out, s, sraw);
                else         ph_attn(t - 125, Vw, Vb, embW, targets, s + 1, sraw);
            }
        }
        grid_sync(nb);
    }
}

// ---------------- launcher ----------------
extern "C" void kernel_launch(void* const* d_in, const int* in_sizes, int n_in,
                              void* d_out, int out_size) {
    const float* eo      = (const float*)d_in[0];
    const float* efs     = (const float*)d_in[1];
    const int*   targets = (const int*)  d_in[2];
    const float* embW    = (const float*)d_in[3];
    const float* Qw      = (const float*)d_in[4];
    const float* Qb      = (const float*)d_in[5];
    const float* Kw      = (const float*)d_in[6];
    const float* Kb      = (const float*)d_in[7];
    const float* Vw      = (const float*)d_in[8];
    const float* Vb      = (const float*)d_in[9];
    const float* Wih0    = (const float*)d_in[10];
    const float* Whh0    = (const float*)d_in[11];
    const float* bih0    = (const float*)d_in[12];
    const float* bhh0    = (const float*)d_in[13];
    const float* Wih1    = (const float*)d_in[14];
    const float* Whh1    = (const float*)d_in[15];
    const float* bih1    = (const float*)d_in[16];
    const float* bhh1    = (const float*)d_in[17];
    const float* Pw0     = (const float*)d_in[18];
    const float* Pb0     = (const float*)d_in[19];
    const float* Pw1     = (const float*)d_in[20];
    const float* Pb1     = (const float*)d_in[21];
    float* out = (float*)d_out;

    int smCount = 148;
    cudaDeviceGetAttribute(&smCount, cudaDevAttrMultiProcessorCount, 0);

    prep_hinit<<<(L * NB * H + 255) / 256, 256>>>(efs);
    eo_to_half<<<(L * T * NB * H / 2 + 255) / 256, 256>>>(eo);
    kproj_gemm<<<dim3(128, 4, 2), 256>>>(eo, Kw, Kb);
    decode_persist<<<2 * smCount, 256>>>(targets, embW, Qw, Qb, Vw, Vb,
                                         Wih0, Whh0, bih0, bhh0,
                                         Wih1, Whh1, bih1, bhh1,
                                         Pw0, Pb0, Pw1, Pb1, out);
}

// round 14
// speedup vs baseline: 1.0482x; 1.0482x over previous
#include <cuda_runtime.h>
#include <cuda_fp16.h>
#include <cstdint>

#define L  2
#define T  128
#define NB 64      // batch N
#define H  512
#define E  256
#define A  200
#define V  1000
#define S  40
#define LT (L*T)   // 256

// ---------------- scratch (device globals) ----------------
__device__ __align__(16) __half g_KprojH[L*T*NB*A];  // (l,t,n,a) fp16
__device__ __align__(16) __half g_eoH[L*T*NB*H];     // fp16 copy of eo
__device__ __align__(16) __half g_qprojH[L*NB*A];    // (l,n,a) fp16
__device__ __align__(16) __half g_xH[(E+H)*NB];      // (k,n) fp16 GRU0 input
__device__ __align__(16) float g_h[2][L][H*NB];      // fp32 recurrent state (k,n)
__device__ __align__(16) __half g_hH[2][L][H*NB];    // fp16 operand copy
__device__ __align__(16) __half g_projH[H*NB];       // (k,n) fp16

// ---------------- helpers ----------------
__device__ __forceinline__ float4 ld_half4(const __half* __restrict__ p) {
    uint2 u = *reinterpret_cast<const uint2*>(p);
    __half2 h0 = *reinterpret_cast<const __half2*>(&u.x);
    __half2 h1 = *reinterpret_cast<const __half2*>(&u.y);
    float2 f0 = __half22float2(h0), f1 = __half22float2(h1);
    return make_float4(f0.x, f0.y, f1.x, f1.y);
}

__device__ __forceinline__ float fast_rcp(float q) {
    float r = __uint_as_float(0x7EF311C3u - __float_as_uint(q));
    r = r * (2.0f - q * r);
    r = r * (2.0f - q * r);
    r = r * (2.0f - q * r);
    return r;
}

__device__ __forceinline__ float tanh_fast(float x) {
    const float c = 7.99881172180175781f;
    x = fminf(fmaxf(x, -c), c);
    float x2 = x * x;
    float p = fmaf(x2, -2.76076847742355e-16f, 2.00018790482477e-13f);
    p = fmaf(x2, p, -8.60467152213735e-11f);
    p = fmaf(x2, p,  5.12229709037114e-08f);
    p = fmaf(x2, p,  1.48572235717979e-05f);
    p = fmaf(x2, p,  6.37261928875436e-04f);
    p = fmaf(x2, p,  4.89352455891786e-03f);
    p = p * x;
    float q = fmaf(x2, 1.19825839466702e-06f, 1.18534705686654e-04f);
    q = fmaf(x2, q, 2.26843463243900e-03f);
    q = fmaf(x2, q, 4.89352518554385e-03f);
    return p * fast_rcp(q);
}

__device__ __forceinline__ float sigmoid_fast(float x) {
    return fmaf(tanh_fast(0.5f * x), 0.5f, 0.5f);
}

// ---------------- prep kernels (once per launch) ----------------
__global__ void prep_hinit(const float* __restrict__ efs) {
    int i = blockIdx.x * 256 + threadIdx.x;        // over L*NB*H
    if (i >= L * NB * H) return;
    int k = i % H;
    int n = (i / H) % NB;
    int l = i / (NB * H);
    float v = efs[i];
    g_h[0][l][k * NB + n] = v;
    g_hH[0][l][k * NB + n] = __float2half(v);
}

__global__ void eo_to_half(const float* __restrict__ eo) {
    int i = blockIdx.x * 256 + threadIdx.x;        // over L*T*NB*H/2
    if (i >= L * T * NB * H / 2) return;
    float2 v = reinterpret_cast<const float2*>(eo)[i];
    reinterpret_cast<__half2*>(g_eoH)[i] = __floats2half2_rn(v.x, v.y);
}

__global__ void kproj_gemm(const float* __restrict__ eo,
                           const float* __restrict__ Kw,
                           const float* __restrict__ Kb) {
    const int l   = blockIdx.z;
    const int tn0 = blockIdx.x * 64;
    const int a0  = blockIdx.y * 64;
    const float* Ab = eo + (size_t)l * (T * NB) * H;
    const float* Bb = Kw + (size_t)l * A * H;
    __shared__ float As[16][64];
    __shared__ float Bs[16][64];
    const int tid = threadIdx.x;
    const int tr = tid >> 4, tc = tid & 15;
    const int lr = tid >> 2;
    const int lk = (tid & 3) * 4;
    float acc[4][4];
    #pragma unroll
    for (int i = 0; i < 4; i++)
        #pragma unroll
        for (int j = 0; j < 4; j++) acc[i][j] = 0.0f;

    for (int k0 = 0; k0 < H; k0 += 16) {
        float4 a4 = *reinterpret_cast<const float4*>(&Ab[(size_t)(tn0 + lr) * H + k0 + lk]);
        As[lk + 0][lr] = a4.x; As[lk + 1][lr] = a4.y;
        As[lk + 2][lr] = a4.z; As[lk + 3][lr] = a4.w;
        float4 b4 = make_float4(0.f, 0.f, 0.f, 0.f);
        if (a0 + lr < A)
            b4 = *reinterpret_cast<const float4*>(&Bb[(size_t)(a0 + lr) * H + k0 + lk]);
        Bs[lk + 0][lr] = b4.x; Bs[lk + 1][lr] = b4.y;
        Bs[lk + 2][lr] = b4.z; Bs[lk + 3][lr] = b4.w;
        __syncthreads();
        #pragma unroll
        for (int kk = 0; kk < 16; kk++) {
            float4 av = *reinterpret_cast<const float4*>(&As[kk][tr * 4]);
            float4 bv = *reinterpret_cast<const float4*>(&Bs[kk][tc * 4]);
            acc[0][0]=fmaf(av.x,bv.x,acc[0][0]); acc[0][1]=fmaf(av.x,bv.y,acc[0][1]);
            acc[0][2]=fmaf(av.x,bv.z,acc[0][2]); acc[0][3]=fmaf(av.x,bv.w,acc[0][3]);
            acc[1][0]=fmaf(av.y,bv.x,acc[1][0]); acc[1][1]=fmaf(av.y,bv.y,acc[1][1]);
            acc[1][2]=fmaf(av.y,bv.z,acc[1][2]); acc[1][3]=fmaf(av.y,bv.w,acc[1][3]);
            acc[2][0]=fmaf(av.z,bv.x,acc[2][0]); acc[2][1]=fmaf(av.z,bv.y,acc[2][1]);
            acc[2][2]=fmaf(av.z,bv.z,acc[2][2]); acc[2][3]=fmaf(av.z,bv.w,acc[2][3]);
            acc[3][0]=fmaf(av.w,bv.x,acc[3][0]); acc[3][1]=fmaf(av.w,bv.y,acc[3][1]);
            acc[3][2]=fmaf(av.w,bv.z,acc[3][2]); acc[3][3]=fmaf(av.w,bv.w,acc[3][3]);
        }
        __syncthreads();
    }
    #pragma unroll
    for (int i = 0; i < 4; i++) {
        int tn = tn0 + tr * 4 + i;
        #pragma unroll
        for (int j = 0; j < 4; j++) {
            int a = a0 + tc * 4 + j;
            if (a < A)
                g_KprojH[(size_t)(l * T * NB + tn) * A + a] =
                    __float2half(acc[i][j] + Kb[l * A + a]);
        }
    }
}

// ============ per-step kernels ============

// qproj: block = (2 a rows, l). grid (100, 2).
__global__ void __launch_bounds__(256, 4)
qproj_row2(const float* __restrict__ Qw, const float* __restrict__ Qb, int cur) {
    __shared__ float sw[8][2][2][16];
    __shared__ float sacc[2][16][64];
    const int a0 = blockIdx.x * 2, l = blockIdx.y;
    const int tid = threadIdx.x;
    const int w = tid >> 5, lane = tid & 31;
    const int half = lane >> 4, ln = lane & 15;
    const int n0 = ln * 4;
    const __half* __restrict__ xin = g_hH[cur][l];
    const float* __restrict__ wbase = Qw + ((size_t)(l * A + a0)) * H;

    float acc[2][4] = {};
    const int kb = w * 64 + half * 32;
    #pragma unroll
    for (int kc = 0; kc < 32; kc += 16) {
        int k0 = kb + kc;
        #pragma unroll
        for (int r = 0; r < 2; r++)
            sw[w][half][r][ln] = wbase[(size_t)r * H + k0 + ln];
        __syncwarp();
        #pragma unroll
        for (int c = 0; c < 16; c++) {
            float4 xv = ld_half4(&xin[(k0 + c) * NB + n0]);
            #pragma unroll
            for (int r = 0; r < 2; r++) {
                float wv = sw[w][half][r][c];
                acc[r][0] = fmaf(wv, xv.x, acc[r][0]);
                acc[r][1] = fmaf(wv, xv.y, acc[r][1]);
                acc[r][2] = fmaf(wv, xv.z, acc[r][2]);
                acc[r][3] = fmaf(wv, xv.w, acc[r][3]);
            }
        }
        __syncwarp();
    }
    const int ws = w * 2 + half;
    #pragma unroll
    for (int r = 0; r < 2; r++)
        *(float4*)&sacc[r][ws][n0] = make_float4(acc[r][0], acc[r][1], acc[r][2], acc[r][3]);
    __syncthreads();
    if (tid < 128) {
        int r = tid >> 6, n = tid & 63;
        float s = 0.f;
        #pragma unroll
        for (int ws2 = 0; ws2 < 16; ws2++) s += sacc[r][ws2][n];
        g_qprojH[((size_t)l * NB + n) * A + a0 + r] = __float2half(s + Qb[l * A + a0 + r]);
    }
}

// attention fused: scores + softmax + context + embedding; block = n (grid 64).
__global__ void __launch_bounds__(256, 4)
attn_fused(const float* __restrict__ Vw, const float* __restrict__ Vb,
           const float* __restrict__ embW, const int* __restrict__ targets, int s) {
    __shared__ float sc[LT];
    __shared__ float wgt[LT];
    __shared__ float red[8];
    const int n = blockIdx.x;
    const int tid = threadIdx.x;
    const int w = tid >> 5, lane = tid & 31;

    // scores: warp w handles lt = w*32 + i
    for (int i = 0; i < 32; i++) {
        int lt = w * 32 + i;
        int l = lt >> 7;
        const __half* kp = g_KprojH + (size_t)(lt * NB + n) * A;
        const __half* qp = g_qprojH + (size_t)(l * NB + n) * A;
        const float* vw = Vw + l * A;
        float acc = 0.f;
        #pragma unroll
        for (int jj = 0; jj < 4; jj++) {
            int a = jj * 64 + lane * 2;
            if (a < A) {
                float2 v = *(const float2*)&vw[a];
                float2 k = __half22float2(*(const __half2*)&kp[a]);
                float2 q = __half22float2(*(const __half2*)&qp[a]);
                acc = fmaf(v.x, tanh_fast(q.x + k.x), acc);
                acc = fmaf(v.y, tanh_fast(q.y + k.y), acc);
            }
        }
        #pragma unroll
        for (int o = 16; o > 0; o >>= 1)
            acc += __shfl_down_sync(0xFFFFFFFFu, acc, o);
        if (lane == 0) sc[lt] = acc + Vb[l];
    }
    __syncthreads();

    // softmax over 256
    float v0 = sc[tid];
    float m = v0;
    #pragma unroll
    for (int o = 16; o > 0; o >>= 1)
        m = fmaxf(m, __shfl_xor_sync(0xFFFFFFFFu, m, o));
    if (lane == 0) red[tid >> 5] = m;
    __syncthreads();
    if (tid < 8) {
        float v = red[tid];
        #pragma unroll
        for (int o = 4; o > 0; o >>= 1)
            v = fmaxf(v, __shfl_xor_sync(0xFFu, v, o, 8));
        if (tid == 0) red[0] = v;
    }
    __syncthreads();
    float mx = red[0];
    float e = __expf(v0 - mx);
    float su = e;
    #pragma unroll
    for (int o = 16; o > 0; o >>= 1)
        su += __shfl_xor_sync(0xFFFFFFFFu, su, o);
    __syncthreads();
    if (lane == 0) red[tid >> 5] = su;
    __syncthreads();
    if (tid < 8) {
        float v = red[tid];
        #pragma unroll
        for (int o = 4; o > 0; o >>= 1)
            v += __shfl_xor_sync(0xFFu, v, o, 8);
        if (tid == 0) red[0] = v;
    }
    __syncthreads();
    wgt[tid] = e * (1.0f / red[0]);
    __syncthreads();

    // context: thread owns h-pair (2*tid, 2*tid+1); 256 thr cover H=512
    const __half2* ep = reinterpret_cast<const __half2*>(g_eoH + (size_t)n * H) + tid;
    float ax = 0.f, ay = 0.f;
    #pragma unroll 16
    for (int lt = 0; lt < LT; lt++) {
        float2 f = __half22float2(ep[(size_t)lt * (NB * H / 2)]);
        float wv = wgt[lt];
        ax = fmaf(wv, f.x, ax);
        ay = fmaf(wv, f.y, ay);
    }
    g_xH[(E + 2 * tid + 0) * NB + n] = __float2half(ax);
    g_xH[(E + 2 * tid + 1) * NB + n] = __float2half(ay);

    int tok = (s == 0) ? 1 : targets[n * S + (s - 1)];
    g_xH[tid * NB + n] = __float2half(fmaxf(embW[(size_t)tok * E + tid], 0.0f));
}

// GRU: block = 2 j rows. grid 256. fp16 operands.
template <int KIN>
__global__ void __launch_bounds__(256, 2)
gru_row2(const float* __restrict__ Wih, const float* __restrict__ Whh,
         const float* __restrict__ bih, const float* __restrict__ bhh,
         int cur, int layer) {
    __shared__ float sw[8][2][6][16];
    __shared__ float sacc[2][4][16][64];
    __shared__ float sgate[2][4][64];
    const int j0 = blockIdx.x * 2;
    const int tid = threadIdx.x;
    const int w = tid >> 5, lane = tid & 31;
    const int half = lane >> 4, ln = lane & 15;
    const int n0 = ln * 4;
    const int nxt = cur ^ 1;

    const __half* __restrict__ xin = (layer == 0) ? g_xH : g_hH[nxt][0];
    const __half* __restrict__ hin = g_hH[cur][layer];
    const float* __restrict__ hprev = g_h[cur][layer];
    float* __restrict__ hout = g_h[nxt][layer];
    __half* __restrict__ houtH = g_hH[nxt][layer];

    float aR[2][4] = {}, aZ[2][4] = {}, aI[2][4] = {}, aH[2][4] = {};

    // x part
    {
        const int kx = KIN / 8;
        const int kb = w * kx + half * (kx / 2);
        #pragma unroll
        for (int kc = 0; kc < kx / 2; kc += 16) {
            int k0 = kb + kc;
            #pragma unroll
            for (int g = 0; g < 6; g++) {
                int jj = g >= 3 ? 1 : 0;
                int gate = g - jj * 3;
                sw[w][half][g][ln] = Wih[((size_t)gate * H + j0 + jj) * KIN + k0 + ln];
            }
            __syncwarp();
            #pragma unroll
            for (int c = 0; c < 16; c++) {
                float4 xv = ld_half4(&xin[(k0 + c) * NB + n0]);
                #pragma unroll
                for (int jj = 0; jj < 2; jj++) {
                    float wR = sw[w][half][jj * 3 + 0][c];
                    float wZ = sw[w][half][jj * 3 + 1][c];
                    float wN = sw[w][half][jj * 3 + 2][c];
                    aR[jj][0]=fmaf(wR,xv.x,aR[jj][0]); aR[jj][1]=fmaf(wR,xv.y,aR[jj][1]);
                    aR[jj][2]=fmaf(wR,xv.z,aR[jj][2]); aR[jj][3]=fmaf(wR,xv.w,aR[jj][3]);
                    aZ[jj][0]=fmaf(wZ,xv.x,aZ[jj][0]); aZ[jj][1]=fmaf(wZ,xv.y,aZ[jj][1]);
                    aZ[jj][2]=fmaf(wZ,xv.z,aZ[jj][2]); aZ[jj][3]=fmaf(wZ,xv.w,aZ[jj][3]);
                    aI[jj][0]=fmaf(wN,xv.x,aI[jj][0]); aI[jj][1]=fmaf(wN,xv.y,aI[jj][1]);
                    aI[jj][2]=fmaf(wN,xv.z,aI[jj][2]); aI[jj][3]=fmaf(wN,xv.w,aI[jj][3]);
                }
            }
            __syncwarp();
        }
    }
    // h part
    {
        const int kb = w * 64 + half * 32;
        #pragma unroll
        for (int kc = 0; kc < 32; kc += 16) {
            int k0 = kb + kc;
            #pragma unroll
            for (int g = 0; g < 6; g++) {
                int jj = g >= 3 ? 1 : 0;
                int gate = g - jj * 3;
                sw[w][half][g][ln] = Whh[((size_t)gate * H + j0 + jj) * H + k0 + ln];
            }
            __syncwarp();
            #pragma unroll
            for (int c = 0; c < 16; c++) {
                float4 xv = ld_half4(&hin[(k0 + c) * NB + n0]);
                #pragma unroll
                for (int jj = 0; jj < 2; jj++) {
                    float wR = sw[w][half][jj * 3 + 0][c];
                    float wZ = sw[w][half][jj * 3 + 1][c];
                    float wN = sw[w][half][jj * 3 + 2][c];
                    aR[jj][0]=fmaf(wR,xv.x,aR[jj][0]); aR[jj][1]=fmaf(wR,xv.y,aR[jj][1]);
                    aR[jj][2]=fmaf(wR,xv.z,aR[jj][2]); aR[jj][3]=fmaf(wR,xv.w,aR[jj][3]);
                    aZ[jj][0]=fmaf(wZ,xv.x,aZ[jj][0]); aZ[jj][1]=fmaf(wZ,xv.y,aZ[jj][1]);
                    aZ[jj][2]=fmaf(wZ,xv.z,aZ[jj][2]); aZ[jj][3]=fmaf(wZ,xv.w,aZ[jj][3]);
                    aH[jj][0]=fmaf(wN,xv.x,aH[jj][0]); aH[jj][1]=fmaf(wN,xv.y,aH[jj][1]);
                    aH[jj][2]=fmaf(wN,xv.z,aH[jj][2]); aH[jj][3]=fmaf(wN,xv.w,aH[jj][3]);
                }
            }
            __syncwarp();
        }
    }
    const int ws = w * 2 + half;
    #pragma unroll
    for (int jj = 0; jj < 2; jj++) {
        *(float4*)&sacc[jj][0][ws][n0] = make_float4(aR[jj][0], aR[jj][1], aR[jj][2], aR[jj][3]);
        *(float4*)&sacc[jj][1][ws][n0] = make_float4(aZ[jj][0], aZ[jj][1], aZ[jj][2], aZ[jj][3]);
        *(float4*)&sacc[jj][2][ws][n0] = make_float4(aI[jj][0], aI[jj][1], aI[jj][2], aI[jj][3]);
        *(float4*)&sacc[jj][3][ws][n0] = make_float4(aH[jj][0], aH[jj][1], aH[jj][2], aH[jj][3]);
    }
    __syncthreads();
    #pragma unroll
    for (int i = 0; i < 2; i++) {
        int idx = tid + 256 * i;          // 0..511
        int jj = idx >> 8;
        int g  = (idx >> 6) & 3;
        int n  = idx & 63;
        float ssum = 0.f;
        #pragma unroll
        for (int ws2 = 0; ws2 < 16; ws2++) ssum += sacc[jj][g][ws2][n];
        sgate[jj][g][n] = ssum;
    }
    __syncthreads();
    if (tid < 128) {
        int jj = tid >> 6, n = tid & 63;
        int j = j0 + jj;
        float r = sigmoid_fast(sgate[jj][0][n] + bih[j] + bhh[j]);
        float z = sigmoid_fast(sgate[jj][1][n] + bih[H + j] + bhh[H + j]);
        float nn = tanh_fast(sgate[jj][2][n] + bih[2 * H + j] +
                             r * (sgate[jj][3][n] + bhh[2 * H + j]));
        float hp = hprev[j * NB + n];
        float hv = fmaf(z, hp - nn, nn);
        hout[j * NB + n] = hv;
        houtH[j * NB + n] = __float2half(hv);
    }
}

// proj: block = 4 j rows. grid 128. relu output to g_projH (fp16).
__global__ void __launch_bounds__(256, 4)
proj_row4(const float* __restrict__ Pw0, const float* __restrict__ Pb0, int cur) {
    __shared__ float sw[8][2][4][16];
    __shared__ float sacc[4][16][64];
    const int j0 = blockIdx.x * 4;
    const int tid = threadIdx.x;
    const int w = tid >> 5, lane = tid & 31;
    const int half = lane >> 4, ln = lane & 15;
    const int n0 = ln * 4;
    const __half* __restrict__ xin = g_hH[cur ^ 1][1];
    const float* __restrict__ wbase = Pw0 + (size_t)j0 * H;

    float acc[4][4] = {};
    const int kb = w * 64 + half * 32;
    #pragma unroll
    for (int kc = 0; kc < 32; kc += 16) {
        int k0 = kb + kc;
        #pragma unroll
        for (int r = 0; r < 4; r++)
            sw[w][half][r][ln] = wbase[(size_t)r * H + k0 + ln];
        __syncwarp();
        #pragma unroll
        for (int c = 0; c < 16; c++) {
            float4 xv = ld_half4(&xin[(k0 + c) * NB + n0]);
            #pragma unroll
            for (int r = 0; r < 4; r++) {
                float wv = sw[w][half][r][c];
                acc[r][0] = fmaf(wv, xv.x, acc[r][0]);
                acc[r][1] = fmaf(wv, xv.y, acc[r][1]);
                acc[r][2] = fmaf(wv, xv.z, acc[r][2]);
                acc[r][3] = fmaf(wv, xv.w, acc[r][3]);
            }
        }
        __syncwarp();
    }
    const int ws = w * 2 + half;
    #pragma unroll
    for (int r = 0; r < 4; r++)
        *(float4*)&sacc[r][ws][n0] = make_float4(acc[r][0], acc[r][1], acc[r][2], acc[r][3]);
    __syncthreads();
    {
        int r = tid >> 6, n = tid & 63;
        float s = 0.f;
        #pragma unroll
        for (int ws2 = 0; ws2 < 16; ws2++) s += sacc[r][ws2][n];
        g_projH[(j0 + r) * NB + n] = __float2half(fmaxf(s + Pb0[j0 + r], 0.f));
    }
}

// logits: block = 4 v rows. grid 250. fp16 proj operand, fp32 out.
__global__ void __launch_bounds__(256, 4)
logits_row4(const float* __restrict__ Pw1, const float* __restrict__ Pb1,
            float* __restrict__ out, int s) {
    __shared__ float sw[8][2][4][16];
    __shared__ float sacc[4][16][64];
    const int v0 = blockIdx.x * 4;
    const int tid = threadIdx.x;
    const int w = tid >> 5, lane = tid & 31;
    const int half = lane >> 4, ln = lane & 15;
    const int n0 = ln * 4;
    const float* __restrict__ wbase = Pw1 + (size_t)v0 * H;

    float acc[4][4] = {};
    const int kb = w * 64 + half * 32;
    #pragma unroll
    for (int kc = 0; kc < 32; kc += 16) {
        int k0 = kb + kc;
        #pragma unroll
        for (int r = 0; r < 4; r++)
            sw[w][half][r][ln] = wbase[(size_t)r * H + k0 + ln];
        __syncwarp();
        #pragma unroll
        for (int c = 0; c < 16; c++) {
            float4 xv = ld_half4(&g_projH[(k0 + c) * NB + n0]);
            #pragma unroll
            for (int r = 0; r < 4; r++) {
                float wv = sw[w][half][r][c];
                acc[r][0] = fmaf(wv, xv.x, acc[r][0]);
                acc[r][1] = fmaf(wv, xv.y, acc[r][1]);
                acc[r][2] = fmaf(wv, xv.z, acc[r][2]);
                acc[r][3] = fmaf(wv, xv.w, acc[r][3]);
            }
        }
        __syncwarp();
    }
    const int ws = w * 2 + half;
    #pragma unroll
    for (int r = 0; r < 4; r++)
        *(float4*)&sacc[r][ws][n0] = make_float4(acc[r][0], acc[r][1], acc[r][2], acc[r][3]);
    __syncthreads();
    {
        int r = tid >> 6, n = tid & 63;
        float s2 = 0.f;
        #pragma unroll
        for (int ws2 = 0; ws2 < 16; ws2++) s2 += sacc[r][ws2][n];
        out[((size_t)n * S + s) * V + v0 + r] = s2 + Pb1[v0 + r];
    }
}

// ---------------- launcher ----------------
extern "C" void kernel_launch(void* const* d_in, const int* in_sizes, int n_in,
                              void* d_out, int out_size) {
    const float* eo      = (const float*)d_in[0];
    const float* efs     = (const float*)d_in[1];
    const int*   targets = (const int*)  d_in[2];
    const float* embW    = (const float*)d_in[3];
    const float* Qw      = (const float*)d_in[4];
    const float* Qb      = (const float*)d_in[5];
    const float* Kw      = (const float*)d_in[6];
    const float* Kb      = (const float*)d_in[7];
    const float* Vw      = (const float*)d_in[8];
    const float* Vb      = (const float*)d_in[9];
    const float* Wih0    = (const float*)d_in[10];
    const float* Whh0    = (const float*)d_in[11];
    const float* bih0    = (const float*)d_in[12];
    const float* bhh0    = (const float*)d_in[13];
    const float* Wih1    = (const float*)d_in[14];
    const float* Whh1    = (const float*)d_in[15];
    const float* bih1    = (const float*)d_in[16];
    const float* bhh1    = (const float*)d_in[17];
    const float* Pw0     = (const float*)d_in[18];
    const float* Pb0     = (const float*)d_in[19];
    const float* Pw1     = (const float*)d_in[20];
    const float* Pb1     = (const float*)d_in[21];
    float* out = (float*)d_out;

    prep_hinit<<<(L * NB * H + 255) / 256, 256>>>(efs);
    eo_to_half<<<(L * T * NB * H / 2 + 255) / 256, 256>>>(eo);
    kproj_gemm<<<dim3(128, 4, 2), 256>>>(eo, Kw, Kb);

    for (int s = 0; s < S; s++) {
        int cur = s & 1;
        qproj_row2<<<dim3(A / 2, L), 256>>>(Qw, Qb, cur);
        attn_fused<<<NB, 256>>>(Vw, Vb, embW, targets, s);
        gru_row2<E + H><<<H / 2, 256>>>(Wih0, Whh0, bih0, bhh0, cur, 0);
        gru_row2<H><<<H / 2, 256>>>(Wih1, Whh1, bih1, bhh1, cur, 1);
        proj_row4<<<H / 4, 256>>>(Pw0, Pb0, cur);
        logits_row4<<<V / 4, 256>>>(Pw1, Pb1, out, s);
    }
}

// round 15
// speedup vs baseline: 1.4406x; 1.3744x over previous
#include <cuda_runtime.h>
#include <cuda_fp16.h>
#include <cstdint>

#define L  2
#define T  128
#define NB 64      // batch N
#define H  512
#define E  256
#define A  200
#define V  1000
#define S  40
#define LT (L*T)   // 256

// ---------------- scratch (device globals) ----------------
__device__ __align__(16) __half g_KprojH[L*T*NB*A];  // (l,t,n,a) fp16
__device__ __align__(16) __half g_eoH[L*T*NB*H];     // fp16 copy of eo
__device__ __align__(16) __half g_qprojH[L*NB*A];    // (l,n,a) fp16
__device__ __align__(16) float g_scores[NB*LT];      // (n, lt)
__device__ __align__(16) __half g_xH[(E+H)*NB];      // (k,n) fp16 GRU0 input
__device__ __align__(16) float g_h[2][L][H*NB];      // fp32 recurrent state (k,n)
__device__ __align__(16) __half g_hH[2][L][H*NB];    // fp16 operand copy
__device__ __align__(16) __half g_projH[H*NB];       // (k,n) fp16

// ---------------- helpers ----------------
__device__ __forceinline__ float4 ld_half4(const __half* __restrict__ p) {
    uint2 u = *reinterpret_cast<const uint2*>(p);
    __half2 h0 = *reinterpret_cast<const __half2*>(&u.x);
    __half2 h1 = *reinterpret_cast<const __half2*>(&u.y);
    float2 f0 = __half22float2(h0), f1 = __half22float2(h1);
    return make_float4(f0.x, f0.y, f1.x, f1.y);
}

__device__ __forceinline__ float fast_rcp(float q) {
    float r = __uint_as_float(0x7EF311C3u - __float_as_uint(q));
    r = r * (2.0f - q * r);
    r = r * (2.0f - q * r);
    r = r * (2.0f - q * r);
    return r;
}

__device__ __forceinline__ float tanh_fast(float x) {
    const float c = 7.99881172180175781f;
    x = fminf(fmaxf(x, -c), c);
    float x2 = x * x;
    float p = fmaf(x2, -2.76076847742355e-16f, 2.00018790482477e-13f);
    p = fmaf(x2, p, -8.60467152213735e-11f);
    p = fmaf(x2, p,  5.12229709037114e-08f);
    p = fmaf(x2, p,  1.48572235717979e-05f);
    p = fmaf(x2, p,  6.37261928875436e-04f);
    p = fmaf(x2, p,  4.89352455891786e-03f);
    p = p * x;
    float q = fmaf(x2, 1.19825839466702e-06f, 1.18534705686654e-04f);
    q = fmaf(x2, q, 2.26843463243900e-03f);
    q = fmaf(x2, q, 4.89352518554385e-03f);
    return p * fast_rcp(q);
}

__device__ __forceinline__ float sigmoid_fast(float x) {
    return fmaf(tanh_fast(0.5f * x), 0.5f, 0.5f);
}

// ---------------- prep kernels (once per launch) ----------------
__global__ void prep_hinit(const float* __restrict__ efs) {
    int i = blockIdx.x * 256 + threadIdx.x;        // over L*NB*H
    if (i >= L * NB * H) return;
    int k = i % H;
    int n = (i / H) % NB;
    int l = i / (NB * H);
    float v = efs[i];
    g_h[0][l][k * NB + n] = v;
    g_hH[0][l][k * NB + n] = __float2half(v);
}

__global__ void eo_to_half(const float* __restrict__ eo) {
    int i = blockIdx.x * 256 + threadIdx.x;        // over L*T*NB*H/2
    if (i >= L * T * NB * H / 2) return;
    float2 v = reinterpret_cast<const float2*>(eo)[i];
    reinterpret_cast<__half2*>(g_eoH)[i] = __floats2half2_rn(v.x, v.y);
}

__global__ void kproj_gemm(const float* __restrict__ eo,
                           const float* __restrict__ Kw,
                           const float* __restrict__ Kb) {
    const int l   = blockIdx.z;
    const int tn0 = blockIdx.x * 64;
    const int a0  = blockIdx.y * 64;
    const float* Ab = eo + (size_t)l * (T * NB) * H;
    const float* Bb = Kw + (size_t)l * A * H;
    __shared__ float As[16][64];
    __shared__ float Bs[16][64];
    const int tid = threadIdx.x;
    const int tr = tid >> 4, tc = tid & 15;
    const int lr = tid >> 2;
    const int lk = (tid & 3) * 4;
    float acc[4][4];
    #pragma unroll
    for (int i = 0; i < 4; i++)
        #pragma unroll
        for (int j = 0; j < 4; j++) acc[i][j] = 0.0f;

    for (int k0 = 0; k0 < H; k0 += 16) {
        float4 a4 = *reinterpret_cast<const float4*>(&Ab[(size_t)(tn0 + lr) * H + k0 + lk]);
        As[lk + 0][lr] = a4.x; As[lk + 1][lr] = a4.y;
        As[lk + 2][lr] = a4.z; As[lk + 3][lr] = a4.w;
        float4 b4 = make_float4(0.f, 0.f, 0.f, 0.f);
        if (a0 + lr < A)
            b4 = *reinterpret_cast<const float4*>(&Bb[(size_t)(a0 + lr) * H + k0 + lk]);
        Bs[lk + 0][lr] = b4.x; Bs[lk + 1][lr] = b4.y;
        Bs[lk + 2][lr] = b4.z; Bs[lk + 3][lr] = b4.w;
        __syncthreads();
        #pragma unroll
        for (int kk = 0; kk < 16; kk++) {
            float4 av = *reinterpret_cast<const float4*>(&As[kk][tr * 4]);
            float4 bv = *reinterpret_cast<const float4*>(&Bs[kk][tc * 4]);
            acc[0][0]=fmaf(av.x,bv.x,acc[0][0]); acc[0][1]=fmaf(av.x,bv.y,acc[0][1]);
            acc[0][2]=fmaf(av.x,bv.z,acc[0][2]); acc[0][3]=fmaf(av.x,bv.w,acc[0][3]);
            acc[1][0]=fmaf(av.y,bv.x,acc[1][0]); acc[1][1]=fmaf(av.y,bv.y,acc[1][1]);
            acc[1][2]=fmaf(av.y,bv.z,acc[1][2]); acc[1][3]=fmaf(av.y,bv.w,acc[1][3]);
            acc[2][0]=fmaf(av.z,bv.x,acc[2][0]); acc[2][1]=fmaf(av.z,bv.y,acc[2][1]);
            acc[2][2]=fmaf(av.z,bv.z,acc[2][2]); acc[2][3]=fmaf(av.z,bv.w,acc[2][3]);
            acc[3][0]=fmaf(av.w,bv.x,acc[3][0]); acc[3][1]=fmaf(av.w,bv.y,acc[3][1]);
            acc[3][2]=fmaf(av.w,bv.z,acc[3][2]); acc[3][3]=fmaf(av.w,bv.w,acc[3][3]);
        }
        __syncthreads();
    }
    #pragma unroll
    for (int i = 0; i < 4; i++) {
        int tn = tn0 + tr * 4 + i;
        #pragma unroll
        for (int j = 0; j < 4; j++) {
            int a = a0 + tc * 4 + j;
            if (a < A)
                g_KprojH[(size_t)(l * T * NB + tn) * A + a] =
                    __float2half(acc[i][j] + Kb[l * A + a]);
        }
    }
}

// ============ device-side phase bodies ============

// qproj body: 2 a-rows; hsel = which h pingpong slot holds the query state.
__device__ __forceinline__ void body_qproj2(int a0, int l,
                                            const float* __restrict__ Qw,
                                            const float* __restrict__ Qb,
                                            int hsel, char* sraw) {
    float (*sw)[2][2][16] = reinterpret_cast<float(*)[2][2][16]>(sraw);       // 2KB
    float (*sacc)[16][64] = reinterpret_cast<float(*)[16][64]>(sraw + 2048);  // 8KB
    const int tid = threadIdx.x;
    const int w = tid >> 5, lane = tid & 31;
    const int half = lane >> 4, ln = lane & 15;
    const int n0 = ln * 4;
    const __half* __restrict__ xin = g_hH[hsel][l];
    const float* __restrict__ wbase = Qw + ((size_t)(l * A + a0)) * H;

    float acc[2][4] = {};
    const int kb = w * 64 + half * 32;
    #pragma unroll
    for (int kc = 0; kc < 32; kc += 16) {
        int k0 = kb + kc;
        #pragma unroll
        for (int r = 0; r < 2; r++)
            sw[w][half][r][ln] = wbase[(size_t)r * H + k0 + ln];
        __syncwarp();
        #pragma unroll
        for (int c = 0; c < 16; c++) {
            float4 xv = ld_half4(&xin[(k0 + c) * NB + n0]);
            #pragma unroll
            for (int r = 0; r < 2; r++) {
                float wv = sw[w][half][r][c];
                acc[r][0] = fmaf(wv, xv.x, acc[r][0]);
                acc[r][1] = fmaf(wv, xv.y, acc[r][1]);
                acc[r][2] = fmaf(wv, xv.z, acc[r][2]);
                acc[r][3] = fmaf(wv, xv.w, acc[r][3]);
            }
        }
        __syncwarp();
    }
    const int ws = w * 2 + half;
    #pragma unroll
    for (int r = 0; r < 2; r++)
        *(float4*)&sacc[r][ws][n0] = make_float4(acc[r][0], acc[r][1], acc[r][2], acc[r][3]);
    __syncthreads();
    if (tid < 128) {
        int r = tid >> 6, n = tid & 63;
        float s = 0.f;
        #pragma unroll
        for (int ws2 = 0; ws2 < 16; ws2++) s += sacc[r][ws2][n];
        g_qprojH[((size_t)l * NB + n) * A + a0 + r] = __float2half(s + Qb[l * A + a0 + r]);
    }
}

// proj body: 4 j-rows; hsel = slot holding h1 written this step.
__device__ __forceinline__ void body_proj4(int j0,
                                           const float* __restrict__ Pw0,
                                           const float* __restrict__ Pb0,
                                           int hsel, char* sraw) {
    float (*sw)[2][4][16] = reinterpret_cast<float(*)[2][4][16]>(sraw);       // 4KB
    float (*sacc)[16][64] = reinterpret_cast<float(*)[16][64]>(sraw + 4096);  // 16KB
    const int tid = threadIdx.x;
    const int w = tid >> 5, lane = tid & 31;
    const int half = lane >> 4, ln = lane & 15;
    const int n0 = ln * 4;
    const __half* __restrict__ xin = g_hH[hsel][1];
    const float* __restrict__ wbase = Pw0 + (size_t)j0 * H;

    float acc[4][4] = {};
    const int kb = w * 64 + half * 32;
    #pragma unroll
    for (int kc = 0; kc < 32; kc += 16) {
        int k0 = kb + kc;
        #pragma unroll
        for (int r = 0; r < 4; r++)
            sw[w][half][r][ln] = wbase[(size_t)r * H + k0 + ln];
        __syncwarp();
        #pragma unroll
        for (int c = 0; c < 16; c++) {
            float4 xv = ld_half4(&xin[(k0 + c) * NB + n0]);
            #pragma unroll
            for (int r = 0; r < 4; r++) {
                float wv = sw[w][half][r][c];
                acc[r][0] = fmaf(wv, xv.x, acc[r][0]);
                acc[r][1] = fmaf(wv, xv.y, acc[r][1]);
                acc[r][2] = fmaf(wv, xv.z, acc[r][2]);
                acc[r][3] = fmaf(wv, xv.w, acc[r][3]);
            }
        }
        __syncwarp();
    }
    const int ws = w * 2 + half;
    #pragma unroll
    for (int r = 0; r < 4; r++)
        *(float4*)&sacc[r][ws][n0] = make_float4(acc[r][0], acc[r][1], acc[r][2], acc[r][3]);
    __syncthreads();
    {
        int r = tid >> 6, n = tid & 63;
        float s = 0.f;
        #pragma unroll
        for (int ws2 = 0; ws2 < 16; ws2++) s += sacc[r][ws2][n];
        g_projH[(j0 + r) * NB + n] = __float2half(fmaxf(s + Pb0[j0 + r], 0.f));
    }
}

// logits body: 4 v-rows, writes out for step s.
__device__ __forceinline__ void body_logits4(int v0,
                                             const float* __restrict__ Pw1,
                                             const float* __restrict__ Pb1,
                                             float* __restrict__ out, int s,
                                             char* sraw) {
    float (*sw)[2][4][16] = reinterpret_cast<float(*)[2][4][16]>(sraw);
    float (*sacc)[16][64] = reinterpret_cast<float(*)[16][64]>(sraw + 4096);
    const int tid = threadIdx.x;
    const int w = tid >> 5, lane = tid & 31;
    const int half = lane >> 4, ln = lane & 15;
    const int n0 = ln * 4;
    const float* __restrict__ wbase = Pw1 + (size_t)v0 * H;

    float acc[4][4] = {};
    const int kb = w * 64 + half * 32;
    #pragma unroll
    for (int kc = 0; kc < 32; kc += 16) {
        int k0 = kb + kc;
        #pragma unroll
        for (int r = 0; r < 4; r++)
            sw[w][half][r][ln] = wbase[(size_t)r * H + k0 + ln];
        __syncwarp();
        #pragma unroll
        for (int c = 0; c < 16; c++) {
            float4 xv = ld_half4(&g_projH[(k0 + c) * NB + n0]);
            #pragma unroll
            for (int r = 0; r < 4; r++) {
                float wv = sw[w][half][r][c];
                acc[r][0] = fmaf(wv, xv.x, acc[r][0]);
                acc[r][1] = fmaf(wv, xv.y, acc[r][1]);
                acc[r][2] = fmaf(wv, xv.z, acc[r][2]);
                acc[r][3] = fmaf(wv, xv.w, acc[r][3]);
            }
        }
        __syncwarp();
    }
    const int ws = w * 2 + half;
    #pragma unroll
    for (int r = 0; r < 4; r++)
        *(float4*)&sacc[r][ws][n0] = make_float4(acc[r][0], acc[r][1], acc[r][2], acc[r][3]);
    __syncthreads();
    {
        int r = tid >> 6, n = tid & 63;
        float s2 = 0.f;
        #pragma unroll
        for (int ws2 = 0; ws2 < 16; ws2++) s2 += sacc[r][ws2][n];
        out[((size_t)n * S + s) * V + v0 + r] = s2 + Pb1[v0 + r];
    }
}

// scores body: block covers (t, l, halfn); 8 warps, warp handles 4 n-rows.
__device__ __forceinline__ void body_scores(int t, int l, int halfn,
                                            const float* __restrict__ Vw,
                                            const float* __restrict__ Vb) {
    const int tid = threadIdx.x;
    const int w = tid >> 5, lane = tid & 31;
    const int lt = l * T + t;
    const float* vw = Vw + l * A;
    const float vb = Vb[l];
    const int n0 = halfn * 32 + w;
    const int n1 = n0 + 8, n2 = n0 + 16, n3 = n0 + 24;
    const __half* kp0 = g_KprojH + (size_t)(lt * NB + n0) * A;
    const __half* kp1 = g_KprojH + (size_t)(lt * NB + n1) * A;
    const __half* kp2 = g_KprojH + (size_t)(lt * NB + n2) * A;
    const __half* kp3 = g_KprojH + (size_t)(lt * NB + n3) * A;
    const __half* qp = g_qprojH + (size_t)l * NB * A;

    float a0 = 0.f, a1 = 0.f, a2 = 0.f, a3 = 0.f;
    #pragma unroll
    for (int i = 0; i < 4; i++) {
        int a = i * 64 + lane * 2;
        if (a < A) {
            float2 v  = *(const float2*)&vw[a];
            float2 k0 = __half22float2(*(const __half2*)&kp0[a]);
            float2 k1 = __half22float2(*(const __half2*)&kp1[a]);
            float2 k2 = __half22float2(*(const __half2*)&kp2[a]);
            float2 k3 = __half22float2(*(const __half2*)&kp3[a]);
            float2 q0 = __half22float2(*(const __half2*)&qp[n0 * A + a]);
            float2 q1 = __half22float2(*(const __half2*)&qp[n1 * A + a]);
            float2 q2 = __half22float2(*(const __half2*)&qp[n2 * A + a]);
            float2 q3 = __half22float2(*(const __half2*)&qp[n3 * A + a]);
            a0 = fmaf(v.x, tanh_fast(q0.x + k0.x), a0);
            a0 = fmaf(v.y, tanh_fast(q0.y + k0.y), a0);
            a1 = fmaf(v.x, tanh_fast(q1.x + k1.x), a1);
            a1 = fmaf(v.y, tanh_fast(q1.y + k1.y), a1);
            a2 = fmaf(v.x, tanh_fast(q2.x + k2.x), a2);
            a2 = fmaf(v.y, tanh_fast(q2.y + k2.y), a2);
            a3 = fmaf(v.x, tanh_fast(q3.x + k3.x), a3);
            a3 = fmaf(v.y, tanh_fast(q3.y + k3.y), a3);
        }
    }
    #pragma unroll
    for (int o = 16; o > 0; o >>= 1) {
        a0 += __shfl_down_sync(0xFFFFFFFFu, a0, o);
        a1 += __shfl_down_sync(0xFFFFFFFFu, a1, o);
        a2 += __shfl_down_sync(0xFFFFFFFFu, a2, o);
        a3 += __shfl_down_sync(0xFFFFFFFFu, a3, o);
    }
    if (lane == 0) {
        g_scores[n0 * LT + lt] = a0 + vb;
        g_scores[n1 * LT + lt] = a1 + vb;
        g_scores[n2 * LT + lt] = a2 + vb;
        g_scores[n3 * LT + lt] = a3 + vb;
    }
}

// ============ merged kernels ============

// K3: blocks [0,128) proj(s); blocks [128,328) qproj(s+1). hsel = slot of h written this step.
__global__ void __launch_bounds__(256, 4)
proj_qproj(const float* __restrict__ Pw0, const float* __restrict__ Pb0,
           const float* __restrict__ Qw, const float* __restrict__ Qb, int hsel) {
    __shared__ __align__(16) char sraw[20480];
    int b = blockIdx.x;
    if (b < 128) {
        body_proj4(b * 4, Pw0, Pb0, hsel, sraw);
    } else {
        int qb = b - 128;            // 0..199
        int l = qb / 100;
        int a0 = (qb % 100) * 2;
        body_qproj2(a0, l, Qw, Qb, hsel, sraw);
    }
}

// K4: blocks [0,250) logits(s); blocks [250,762) scores(s+1).
__global__ void __launch_bounds__(256, 4)
logits_scores(const float* __restrict__ Pw1, const float* __restrict__ Pb1,
              float* __restrict__ out, int s,
              const float* __restrict__ Vw, const float* __restrict__ Vb) {
    __shared__ __align__(16) char sraw[20480];
    int b = blockIdx.x;
    if (b < 250) {
        body_logits4(b * 4, Pw1, Pb1, out, s, sraw);
    } else {
        int sb = b - 250;            // 0..511
        int l = sb >> 8;
        int rr = sb & 255;
        body_scores(rr >> 1, l, rr & 1, Vw, Vb);
    }
}

// standalone qproj / scores for the prologue
__global__ void __launch_bounds__(256, 4)
qproj_k(const float* __restrict__ Qw, const float* __restrict__ Qb, int hsel) {
    __shared__ __align__(16) char sraw[10240];
    int qb = blockIdx.x;
    int l = qb / 100;
    int a0 = (qb % 100) * 2;
    body_qproj2(a0, l, Qw, Qb, hsel, sraw);
}

__global__ void __launch_bounds__(256, 4)
scores_k(const float* __restrict__ Vw, const float* __restrict__ Vb) {
    int sb = blockIdx.x;
    int l = sb >> 8;
    int rr = sb & 255;
    body_scores(rr >> 1, l, rr & 1, Vw, Vb);
}

// softmax + context + embedding; one block per n (grid 64, 256 thr)
__global__ void __launch_bounds__(256, 6)
context_v3(const float* __restrict__ embW,
           const int* __restrict__ targets, int s) {
    __shared__ float w[LT];
    __shared__ float red[8];
    int n = blockIdx.x;
    int tid = threadIdx.x;
    int lane = tid & 31;

    float sc = g_scores[n * LT + tid];
    float m = sc;
    #pragma unroll
    for (int o = 16; o > 0; o >>= 1)
        m = fmaxf(m, __shfl_xor_sync(0xFFFFFFFFu, m, o));
    if (lane == 0) red[tid >> 5] = m;
    __syncthreads();
    if (tid < 8) {
        float v = red[tid];
        #pragma unroll
        for (int o = 4; o > 0; o >>= 1)
            v = fmaxf(v, __shfl_xor_sync(0xFFu, v, o, 8));
        if (tid == 0) red[0] = v;
    }
    __syncthreads();
    float mx = red[0];
    float e = __expf(sc - mx);
    float su = e;
    #pragma unroll
    for (int o = 16; o > 0; o >>= 1)
        su += __shfl_xor_sync(0xFFFFFFFFu, su, o);
    __syncthreads();
    if (lane == 0) red[tid >> 5] = su;
    __syncthreads();
    if (tid < 8) {
        float v = red[tid];
        #pragma unroll
        for (int o = 4; o > 0; o >>= 1)
            v += __shfl_xor_sync(0xFFu, v, o, 8);
        if (tid == 0) red[0] = v;
    }
    __syncthreads();
    w[tid] = e * (1.0f / red[0]);
    __syncthreads();

    const __half2* ep = reinterpret_cast<const __half2*>(g_eoH + (size_t)n * H) + tid;
    float ax = 0.f, ay = 0.f;
    #pragma unroll 16
    for (int lt = 0; lt < LT; lt++) {
        float2 f = __half22float2(ep[(size_t)lt * (NB * H / 2)]);
        float wv = w[lt];
        ax = fmaf(wv, f.x, ax);
        ay = fmaf(wv, f.y, ay);
    }
    g_xH[(E + 2 * tid + 0) * NB + n] = __float2half(ax);
    g_xH[(E + 2 * tid + 1) * NB + n] = __float2half(ay);

    int tok = (s == 0) ? 1 : targets[n * S + (s - 1)];
    g_xH[tid * NB + n] = __float2half(fmaxf(embW[(size_t)tok * E + tid], 0.0f));
}

// GRU: block = 2 j rows. grid 256. fp16 operands.
template <int KIN>
__global__ void __launch_bounds__(256, 2)
gru_row2(const float* __restrict__ Wih, const float* __restrict__ Whh,
         const float* __restrict__ bih, const float* __restrict__ bhh,
         int cur, int layer) {
    __shared__ float sw[8][2][6][16];
    __shared__ float sacc[2][4][16][64];
    __shared__ float sgate[2][4][64];
    const int j0 = blockIdx.x * 2;
    const int tid = threadIdx.x;
    const int w = tid >> 5, lane = tid & 31;
    const int half = lane >> 4, ln = lane & 15;
    const int n0 = ln * 4;
    const int nxt = cur ^ 1;

    const __half* __restrict__ xin = (layer == 0) ? g_xH : g_hH[nxt][0];
    const __half* __restrict__ hin = g_hH[cur][layer];
    const float* __restrict__ hprev = g_h[cur][layer];
    float* __restrict__ hout = g_h[nxt][layer];
    __half* __restrict__ houtH = g_hH[nxt][layer];

    float aR[2][4] = {}, aZ[2][4] = {}, aI[2][4] = {}, aH[2][4] = {};

    // x part
    {
        const int kx = KIN / 8;
        const int kb = w * kx + half * (kx / 2);
        #pragma unroll
        for (int kc = 0; kc < kx / 2; kc += 16) {
            int k0 = kb + kc;
            #pragma unroll
            for (int g = 0; g < 6; g++) {
                int jj = g >= 3 ? 1 : 0;
                int gate = g - jj * 3;
                sw[w][half][g][ln] = Wih[((size_t)gate * H + j0 + jj) * KIN + k0 + ln];
            }
            __syncwarp();
            #pragma unroll
            for (int c = 0; c < 16; c++) {
                float4 xv = ld_half4(&xin[(k0 + c) * NB + n0]);
                #pragma unroll
                for (int jj = 0; jj < 2; jj++) {
                    float wR = sw[w][half][jj * 3 + 0][c];
                    float wZ = sw[w][half][jj * 3 + 1][c];
                    float wN = sw[w][half][jj * 3 + 2][c];
                    aR[jj][0]=fmaf(wR,xv.x,aR[jj][0]); aR[jj][1]=fmaf(wR,xv.y,aR[jj][1]);
                    aR[jj][2]=fmaf(wR,xv.z,aR[jj][2]); aR[jj][3]=fmaf(wR,xv.w,aR[jj][3]);
                    aZ[jj][0]=fmaf(wZ,xv.x,aZ[jj][0]); aZ[jj][1]=fmaf(wZ,xv.y,aZ[jj][1]);
                    aZ[jj][2]=fmaf(wZ,xv.z,aZ[jj][2]); aZ[jj][3]=fmaf(wZ,xv.w,aZ[jj][3]);
                    aI[jj][0]=fmaf(wN,xv.x,aI[jj][0]); aI[jj][1]=fmaf(wN,xv.y,aI[jj][1]);
                    aI[jj][2]=fmaf(wN,xv.z,aI[jj][2]); aI[jj][3]=fmaf(wN,xv.w,aI[jj][3]);
                }
            }
            __syncwarp();
        }
    }
    // h part
    {
        const int kb = w * 64 + half * 32;
        #pragma unroll
        for (int kc = 0; kc < 32; kc += 16) {
            int k0 = kb + kc;
            #pragma unroll
            for (int g = 0; g < 6; g++) {
                int jj = g >= 3 ? 1 : 0;
                int gate = g - jj * 3;
                sw[w][half][g][ln] = Whh[((size_t)gate * H + j0 + jj) * H + k0 + ln];
            }
            __syncwarp();
            #pragma unroll
            for (int c = 0; c < 16; c++) {
                float4 xv = ld_half4(&hin[(k0 + c) * NB + n0]);
                #pragma unroll
                for (int jj = 0; jj < 2; jj++) {
                    float wR = sw[w][half][jj * 3 + 0][c];
                    float wZ = sw[w][half][jj * 3 + 1][c];
                    float wN = sw[w][half][jj * 3 + 2][c];
                    aR[jj][0]=fmaf(wR,xv.x,aR[jj][0]); aR[jj][1]=fmaf(wR,xv.y,aR[jj][1]);
                    aR[jj][2]=fmaf(wR,xv.z,aR[jj][2]); aR[jj][3]=fmaf(wR,xv.w,aR[jj][3]);
                    aZ[jj][0]=fmaf(wZ,xv.x,aZ[jj][0]); aZ[jj][1]=fmaf(wZ,xv.y,aZ[jj][1]);
                    aZ[jj][2]=fmaf(wZ,xv.z,aZ[jj][2]); aZ[jj][3]=fmaf(wZ,xv.w,aZ[jj][3]);
                    aH[jj][0]=fmaf(wN,xv.x,aH[jj][0]); aH[jj][1]=fmaf(wN,xv.y,aH[jj][1]);
                    aH[jj][2]=fmaf(wN,xv.z,aH[jj][2]); aH[jj][3]=fmaf(wN,xv.w,aH[jj][3]);
                }
            }
            __syncwarp();
        }
    }
    const int ws = w * 2 + half;
    #pragma unroll
    for (int jj = 0; jj < 2; jj++) {
        *(float4*)&sacc[jj][0][ws][n0] = make_float4(aR[jj][0], aR[jj][1], aR[jj][2], aR[jj][3]);
        *(float4*)&sacc[jj][1][ws][n0] = make_float4(aZ[jj][0], aZ[jj][1], aZ[jj][2], aZ[jj][3]);
        *(float4*)&sacc[jj][2][ws][n0] = make_float4(aI[jj][0], aI[jj][1], aI[jj][2], aI[jj][3]);
        *(float4*)&sacc[jj][3][ws][n0] = make_float4(aH[jj][0], aH[jj][1], aH[jj][2], aH[jj][3]);
    }
    __syncthreads();
    #pragma unroll
    for (int i = 0; i < 2; i++) {
        int idx = tid + 256 * i;          // 0..511
        int jj = idx >> 8;
        int g  = (idx >> 6) & 3;
        int n  = idx & 63;
        float ssum = 0.f;
        #pragma unroll
        for (int ws2 = 0; ws2 < 16; ws2++) ssum += sacc[jj][g][ws2][n];
        sgate[jj][g][n] = ssum;
    }
    __syncthreads();
    if (tid < 128) {
        int jj = tid >> 6, n = tid & 63;
        int j = j0 + jj;
        float r = sigmoid_fast(sgate[jj][0][n] + bih[j] + bhh[j]);
        float z = sigmoid_fast(sgate[jj][1][n] + bih[H + j] + bhh[H + j]);
        float nn = tanh_fast(sgate[jj][2][n] + bih[2 * H + j] +
                             r * (sgate[jj][3][n] + bhh[2 * H + j]));
        float hp = hprev[j * NB + n];
        float hv = fmaf(z, hp - nn, nn);
        hout[j * NB + n] = hv;
        houtH[j * NB + n] = __float2half(hv);
    }
}

// standalone proj / logits for the final step
__global__ void __launch_bounds__(256, 4)
proj_k(const float* __restrict__ Pw0, const float* __restrict__ Pb0, int hsel) {
    __shared__ __align__(16) char sraw[20480];
    body_proj4(blockIdx.x * 4, Pw0, Pb0, hsel, sraw);
}

__global__ void __launch_bounds__(256, 4)
logits_k(const float* __restrict__ Pw1, const float* __restrict__ Pb1,
         float* __restrict__ out, int s) {
    __shared__ __align__(16) char sraw[20480];
    body_logits4(blockIdx.x * 4, Pw1, Pb1, out, s, sraw);
}

// ---------------- launcher ----------------
extern "C" void kernel_launch(void* const* d_in, const int* in_sizes, int n_in,
                              void* d_out, int out_size) {
    const float* eo      = (const float*)d_in[0];
    const float* efs     = (const float*)d_in[1];
    const int*   targets = (const int*)  d_in[2];
    const float* embW    = (const float*)d_in[3];
    const float* Qw      = (const float*)d_in[4];
    const float* Qb      = (const float*)d_in[5];
    const float* Kw      = (const float*)d_in[6];
    const float* Kb      = (const float*)d_in[7];
    const float* Vw      = (const float*)d_in[8];
    const float* Vb      = (const float*)d_in[9];
    const float* Wih0    = (const float*)d_in[10];
    const float* Whh0    = (const float*)d_in[11];
    const float* bih0    = (const float*)d_in[12];
    const float* bhh0    = (const float*)d_in[13];
    const float* Wih1    = (const float*)d_in[14];
    const float* Whh1    = (const float*)d_in[15];
    const float* bih1    = (const float*)d_in[16];
    const float* bhh1    = (const float*)d_in[17];
    const float* Pw0     = (const float*)d_in[18];
    const float* Pb0     = (const float*)d_in[19];
    const float* Pw1     = (const float*)d_in[20];
    const float* Pb1     = (const float*)d_in[21];
    float* out = (float*)d_out;

    prep_hinit<<<(L * NB * H + 255) / 256, 256>>>(efs);
    eo_to_half<<<(L * T * NB * H / 2 + 255) / 256, 256>>>(eo);
    kproj_gemm<<<dim3(128, 4, 2), 256>>>(eo, Kw, Kb);

    // prologue: attention inputs for step 0 (h slot 0)
    qproj_k<<<200, 256>>>(Qw, Qb, 0);
    scores_k<<<512, 256>>>(Vw, Vb);
    context_v3<<<NB, 256>>>(embW, targets, 0);

    for (int s = 0; s < S; s++) {
        int cur = s & 1;
        int nxt = cur ^ 1;
        gru_row2<E + H><<<H / 2, 256>>>(Wih0, Whh0, bih0, bhh0, cur, 0);
        gru_row2<H><<<H / 2, 256>>>(Wih1, Whh1, bih1, bhh1, cur, 1);
        if (s < S - 1) {
            proj_qproj<<<328, 256>>>(Pw0, Pb0, Qw, Qb, nxt);
            logits_scores<<<762, 256>>>(Pw1, Pb1, out, s, Vw, Vb);
            context_v3<<<NB, 256>>>(embW, targets, s + 1);
        } else {
            proj_k<<<H / 4, 256>>>(Pw0, Pb0, nxt);
            logits_k<<<V / 4, 256>>>(Pw1, Pb1, out, s);
        }
    }
}

// round 16
// speedup vs baseline: 1.5199x; 1.0550x over previous
#include <cuda_runtime.h>
#include <cuda_fp16.h>
#include <cstdint>

#define L  2
#define T  128
#define NB 64      // batch N
#define H  512
#define E  256
#define A  200
#define V  1000
#define S  40
#define LT (L*T)   // 256

// ---------------- scratch (device globals) ----------------
__device__ __align__(16) __half g_KprojH[L*T*NB*A];  // (l,t,n,a) fp16
__device__ __align__(16) __half g_eoH[L*T*NB*H];     // fp16 copy of eo
__device__ __align__(16) __half g_qprojH[L*NB*A];    // (l,n,a) fp16
__device__ __align__(16) float g_scores[NB*LT];      // (n, lt)
__device__ __align__(16) __half g_xH[(E+H)*NB];      // (k,n) fp16 GRU0 input
__device__ __align__(16) float g_h[2][L][H*NB];      // fp32 recurrent state (k,n)
__device__ __align__(16) __half g_hH[2][L][H*NB];    // fp16 operand copy
__device__ __align__(16) __half g_projH[H*NB];       // (k,n) fp16

// ---------------- helpers ----------------
__device__ __forceinline__ void pdl_sync() {
#if defined(__CUDA_ARCH__) && __CUDA_ARCH__ >= 900
    cudaGridDependencySynchronize();
#endif
}

__device__ __forceinline__ float4 ld_half4(const __half* __restrict__ p) {
    uint2 u = *reinterpret_cast<const uint2*>(p);
    __half2 h0 = *reinterpret_cast<const __half2*>(&u.x);
    __half2 h1 = *reinterpret_cast<const __half2*>(&u.y);
    float2 f0 = __half22float2(h0), f1 = __half22float2(h1);
    return make_float4(f0.x, f0.y, f1.x, f1.y);
}

__device__ __forceinline__ float fast_rcp(float q) {
    float r = __uint_as_float(0x7EF311C3u - __float_as_uint(q));
    r = r * (2.0f - q * r);
    r = r * (2.0f - q * r);
    r = r * (2.0f - q * r);
    return r;
}

__device__ __forceinline__ float tanh_fast(float x) {
    const float c = 7.99881172180175781f;
    x = fminf(fmaxf(x, -c), c);
    float x2 = x * x;
    float p = fmaf(x2, -2.76076847742355e-16f, 2.00018790482477e-13f);
    p = fmaf(x2, p, -8.60467152213735e-11f);
    p = fmaf(x2, p,  5.12229709037114e-08f);
    p = fmaf(x2, p,  1.48572235717979e-05f);
    p = fmaf(x2, p,  6.37261928875436e-04f);
    p = fmaf(x2, p,  4.89352455891786e-03f);
    p = p * x;
    float q = fmaf(x2, 1.19825839466702e-06f, 1.18534705686654e-04f);
    q = fmaf(x2, q, 2.26843463243900e-03f);
    q = fmaf(x2, q, 4.89352518554385e-03f);
    return p * fast_rcp(q);
}

__device__ __forceinline__ float sigmoid_fast(float x) {
    return fmaf(tanh_fast(0.5f * x), 0.5f, 0.5f);
}

// ---------------- prep kernels (once per launch) ----------------
__global__ void prep_hinit(const float* __restrict__ efs) {
    int i = blockIdx.x * 256 + threadIdx.x;        // over L*NB*H
    if (i >= L * NB * H) return;
    int k = i % H;
    int n = (i / H) % NB;
    int l = i / (NB * H);
    float v = efs[i];
    g_h[0][l][k * NB + n] = v;
    g_hH[0][l][k * NB + n] = __float2half(v);
}

__global__ void eo_to_half(const float* __restrict__ eo) {
    int i = blockIdx.x * 256 + threadIdx.x;        // over L*T*NB*H/2
    if (i >= L * T * NB * H / 2) return;
    float2 v = reinterpret_cast<const float2*>(eo)[i];
    reinterpret_cast<__half2*>(g_eoH)[i] = __floats2half2_rn(v.x, v.y);
}

__global__ void kproj_gemm(const float* __restrict__ eo,
                           const float* __restrict__ Kw,
                           const float* __restrict__ Kb) {
    const int l   = blockIdx.z;
    const int tn0 = blockIdx.x * 64;
    const int a0  = blockIdx.y * 64;
    const float* Ab = eo + (size_t)l * (T * NB) * H;
    const float* Bb = Kw + (size_t)l * A * H;
    __shared__ float As[16][64];
    __shared__ float Bs[16][64];
    const int tid = threadIdx.x;
    const int tr = tid >> 4, tc = tid & 15;
    const int lr = tid >> 2;
    const int lk = (tid & 3) * 4;
    float acc[4][4];
    #pragma unroll
    for (int i = 0; i < 4; i++)
        #pragma unroll
        for (int j = 0; j < 4; j++) acc[i][j] = 0.0f;

    for (int k0 = 0; k0 < H; k0 += 16) {
        float4 a4 = *reinterpret_cast<const float4*>(&Ab[(size_t)(tn0 + lr) * H + k0 + lk]);
        As[lk + 0][lr] = a4.x; As[lk + 1][lr] = a4.y;
        As[lk + 2][lr] = a4.z; As[lk + 3][lr] = a4.w;
        float4 b4 = make_float4(0.f, 0.f, 0.f, 0.f);
        if (a0 + lr < A)
            b4 = *reinterpret_cast<const float4*>(&Bb[(size_t)(a0 + lr) * H + k0 + lk]);
        Bs[lk + 0][lr] = b4.x; Bs[lk + 1][lr] = b4.y;
        Bs[lk + 2][lr] = b4.z; Bs[lk + 3][lr] = b4.w;
        __syncthreads();
        #pragma unroll
        for (int kk = 0; kk < 16; kk++) {
            float4 av = *reinterpret_cast<const float4*>(&As[kk][tr * 4]);
            float4 bv = *reinterpret_cast<const float4*>(&Bs[kk][tc * 4]);
            acc[0][0]=fmaf(av.x,bv.x,acc[0][0]); acc[0][1]=fmaf(av.x,bv.y,acc[0][1]);
            acc[0][2]=fmaf(av.x,bv.z,acc[0][2]); acc[0][3]=fmaf(av.x,bv.w,acc[0][3]);
            acc[1][0]=fmaf(av.y,bv.x,acc[1][0]); acc[1][1]=fmaf(av.y,bv.y,acc[1][1]);
            acc[1][2]=fmaf(av.y,bv.z,acc[1][2]); acc[1][3]=fmaf(av.y,bv.w,acc[1][3]);
            acc[2][0]=fmaf(av.z,bv.x,acc[2][0]); acc[2][1]=fmaf(av.z,bv.y,acc[2][1]);
            acc[2][2]=fmaf(av.z,bv.z,acc[2][2]); acc[2][3]=fmaf(av.z,bv.w,acc[2][3]);
            acc[3][0]=fmaf(av.w,bv.x,acc[3][0]); acc[3][1]=fmaf(av.w,bv.y,acc[3][1]);
            acc[3][2]=fmaf(av.w,bv.z,acc[3][2]); acc[3][3]=fmaf(av.w,bv.w,acc[3][3]);
        }
        __syncthreads();
    }
    #pragma unroll
    for (int i = 0; i < 4; i++) {
        int tn = tn0 + tr * 4 + i;
        #pragma unroll
        for (int j = 0; j < 4; j++) {
            int a = a0 + tc * 4 + j;
            if (a < A)
                g_KprojH[(size_t)(l * T * NB + tn) * A + a] =
                    __float2half(acc[i][j] + Kb[l * A + a]);
        }
    }
}

// ============ device-side phase bodies ============

__device__ __forceinline__ void body_qproj2(int a0, int l,
                                            const float* __restrict__ Qw,
                                            const float* __restrict__ Qb,
                                            int hsel, char* sraw) {
    float (*sw)[2][2][16] = reinterpret_cast<float(*)[2][2][16]>(sraw);
    float (*sacc)[16][64] = reinterpret_cast<float(*)[16][64]>(sraw + 2048);
    const int tid = threadIdx.x;
    const int w = tid >> 5, lane = tid & 31;
    const int half = lane >> 4, ln = lane & 15;
    const int n0 = ln * 4;
    const __half* __restrict__ xin = g_hH[hsel][l];
    const float* __restrict__ wbase = Qw + ((size_t)(l * A + a0)) * H;

    float acc[2][4] = {};
    const int kb = w * 64 + half * 32;
    #pragma unroll
    for (int kc = 0; kc < 32; kc += 16) {
        int k0 = kb + kc;
        #pragma unroll
        for (int r = 0; r < 2; r++)
            sw[w][half][r][ln] = wbase[(size_t)r * H + k0 + ln];
        __syncwarp();
        #pragma unroll
        for (int c = 0; c < 16; c++) {
            float4 xv = ld_half4(&xin[(k0 + c) * NB + n0]);
            #pragma unroll
            for (int r = 0; r < 2; r++) {
                float wv = sw[w][half][r][c];
                acc[r][0] = fmaf(wv, xv.x, acc[r][0]);
                acc[r][1] = fmaf(wv, xv.y, acc[r][1]);
                acc[r][2] = fmaf(wv, xv.z, acc[r][2]);
                acc[r][3] = fmaf(wv, xv.w, acc[r][3]);
            }
        }
        __syncwarp();
    }
    const int ws = w * 2 + half;
    #pragma unroll
    for (int r = 0; r < 2; r++)
        *(float4*)&sacc[r][ws][n0] = make_float4(acc[r][0], acc[r][1], acc[r][2], acc[r][3]);
    __syncthreads();
    if (tid < 128) {
        int r = tid >> 6, n = tid & 63;
        float s = 0.f;
        #pragma unroll
        for (int ws2 = 0; ws2 < 16; ws2++) s += sacc[r][ws2][n];
        g_qprojH[((size_t)l * NB + n) * A + a0 + r] = __float2half(s + Qb[l * A + a0 + r]);
    }
}

__device__ __forceinline__ void body_proj4(int j0,
                                           const float* __restrict__ Pw0,
                                           const float* __restrict__ Pb0,
                                           int hsel, char* sraw) {
    float (*sw)[2][4][16] = reinterpret_cast<float(*)[2][4][16]>(sraw);
    float (*sacc)[16][64] = reinterpret_cast<float(*)[16][64]>(sraw + 4096);
    const int tid = threadIdx.x;
    const int w = tid >> 5, lane = tid & 31;
    const int half = lane >> 4, ln = lane & 15;
    const int n0 = ln * 4;
    const __half* __restrict__ xin = g_hH[hsel][1];
    const float* __restrict__ wbase = Pw0 + (size_t)j0 * H;

    float acc[4][4] = {};
    const int kb = w * 64 + half * 32;
    #pragma unroll
    for (int kc = 0; kc < 32; kc += 16) {
        int k0 = kb + kc;
        #pragma unroll
        for (int r = 0; r < 4; r++)
            sw[w][half][r][ln] = wbase[(size_t)r * H + k0 + ln];
        __syncwarp();
        #pragma unroll
        for (int c = 0; c < 16; c++) {
            float4 xv = ld_half4(&xin[(k0 + c) * NB + n0]);
            #pragma unroll
            for (int r = 0; r < 4; r++) {
                float wv = sw[w][half][r][c];
                acc[r][0] = fmaf(wv, xv.x, acc[r][0]);
                acc[r][1] = fmaf(wv, xv.y, acc[r][1]);
                acc[r][2] = fmaf(wv, xv.z, acc[r][2]);
                acc[r][3] = fmaf(wv, xv.w, acc[r][3]);
            }
        }
        __syncwarp();
    }
    const int ws = w * 2 + half;
    #pragma unroll
    for (int r = 0; r < 4; r++)
        *(float4*)&sacc[r][ws][n0] = make_float4(acc[r][0], acc[r][1], acc[r][2], acc[r][3]);
    __syncthreads();
    {
        int r = tid >> 6, n = tid & 63;
        float s = 0.f;
        #pragma unroll
        for (int ws2 = 0; ws2 < 16; ws2++) s += sacc[r][ws2][n];
        g_projH[(j0 + r) * NB + n] = __float2half(fmaxf(s + Pb0[j0 + r], 0.f));
    }
}

__device__ __forceinline__ void body_logits4(int v0,
                                             const float* __restrict__ Pw1,
                                             const float* __restrict__ Pb1,
                                             float* __restrict__ out, int s,
                                             char* sraw) {
    float (*sw)[2][4][16] = reinterpret_cast<float(*)[2][4][16]>(sraw);
    float (*sacc)[16][64] = reinterpret_cast<float(*)[16][64]>(sraw + 4096);
    const int tid = threadIdx.x;
    const int w = tid >> 5, lane = tid & 31;
    const int half = lane >> 4, ln = lane & 15;
    const int n0 = ln * 4;
    const float* __restrict__ wbase = Pw1 + (size_t)v0 * H;

    float acc[4][4] = {};
    const int kb = w * 64 + half * 32;
    #pragma unroll
    for (int kc = 0; kc < 32; kc += 16) {
        int k0 = kb + kc;
        #pragma unroll
        for (int r = 0; r < 4; r++)
            sw[w][half][r][ln] = wbase[(size_t)r * H + k0 + ln];
        __syncwarp();
        #pragma unroll
        for (int c = 0; c < 16; c++) {
            float4 xv = ld_half4(&g_projH[(k0 + c) * NB + n0]);
            #pragma unroll
            for (int r = 0; r < 4; r++) {
                float wv = sw[w][half][r][c];
                acc[r][0] = fmaf(wv, xv.x, acc[r][0]);
                acc[r][1] = fmaf(wv, xv.y, acc[r][1]);
                acc[r][2] = fmaf(wv, xv.z, acc[r][2]);
                acc[r][3] = fmaf(wv, xv.w, acc[r][3]);
            }
        }
        __syncwarp();
    }
    const int ws = w * 2 + half;
    #pragma unroll
    for (int r = 0; r < 4; r++)
        *(float4*)&sacc[r][ws][n0] = make_float4(acc[r][0], acc[r][1], acc[r][2], acc[r][3]);
    __syncthreads();
    {
        int r = tid >> 6, n = tid & 63;
        float s2 = 0.f;
        #pragma unroll
        for (int ws2 = 0; ws2 < 16; ws2++) s2 += sacc[r][ws2][n];
        out[((size_t)n * S + s) * V + v0 + r] = s2 + Pb1[v0 + r];
    }
}

__device__ __forceinline__ void body_scores(int t, int l, int halfn,
                                            const float* __restrict__ Vw,
                                            const float* __restrict__ Vb) {
    const int tid = threadIdx.x;
    const int w = tid >> 5, lane = tid & 31;
    const int lt = l * T + t;
    const float* vw = Vw + l * A;
    const float vb = Vb[l];
    const int n0 = halfn * 32 + w;
    const int n1 = n0 + 8, n2 = n0 + 16, n3 = n0 + 24;
    const __half* kp0 = g_KprojH + (size_t)(lt * NB + n0) * A;
    const __half* kp1 = g_KprojH + (size_t)(lt * NB + n1) * A;
    const __half* kp2 = g_KprojH + (size_t)(lt * NB + n2) * A;
    const __half* kp3 = g_KprojH + (size_t)(lt * NB + n3) * A;
    const __half* qp = g_qprojH + (size_t)l * NB * A;

    float a0 = 0.f, a1 = 0.f, a2 = 0.f, a3 = 0.f;
    #pragma unroll
    for (int i = 0; i < 4; i++) {
        int a = i * 64 + lane * 2;
        if (a < A) {
            float2 v  = *(const float2*)&vw[a];
            float2 k0 = __half22float2(*(const __half2*)&kp0[a]);
            float2 k1 = __half22float2(*(const __half2*)&kp1[a]);
            float2 k2 = __half22float2(*(const __half2*)&kp2[a]);
            float2 k3 = __half22float2(*(const __half2*)&kp3[a]);
            float2 q0 = __half22float2(*(const __half2*)&qp[n0 * A + a]);
            float2 q1 = __half22float2(*(const __half2*)&qp[n1 * A + a]);
            float2 q2 = __half22float2(*(const __half2*)&qp[n2 * A + a]);
            float2 q3 = __half22float2(*(const __half2*)&qp[n3 * A + a]);
            a0 = fmaf(v.x, tanh_fast(q0.x + k0.x), a0);
            a0 = fmaf(v.y, tanh_fast(q0.y + k0.y), a0);
            a1 = fmaf(v.x, tanh_fast(q1.x + k1.x), a1);
            a1 = fmaf(v.y, tanh_fast(q1.y + k1.y), a1);
            a2 = fmaf(v.x, tanh_fast(q2.x + k2.x), a2);
            a2 = fmaf(v.y, tanh_fast(q2.y + k2.y), a2);
            a3 = fmaf(v.x, tanh_fast(q3.x + k3.x), a3);
            a3 = fmaf(v.y, tanh_fast(q3.y + k3.y), a3);
        }
    }
    #pragma unroll
    for (int o = 16; o > 0; o >>= 1) {
        a0 += __shfl_down_sync(0xFFFFFFFFu, a0, o);
        a1 += __shfl_down_sync(0xFFFFFFFFu, a1, o);
        a2 += __shfl_down_sync(0xFFFFFFFFu, a2, o);
        a3 += __shfl_down_sync(0xFFFFFFFFu, a3, o);
    }
    if (lane == 0) {
        g_scores[n0 * LT + lt] = a0 + vb;
        g_scores[n1 * LT + lt] = a1 + vb;
        g_scores[n2 * LT + lt] = a2 + vb;
        g_scores[n3 * LT + lt] = a3 + vb;
    }
}

// ============ merged kernels ============

__global__ void __launch_bounds__(256, 4)
proj_qproj(const float* __restrict__ Pw0, const float* __restrict__ Pb0,
           const float* __restrict__ Qw, const float* __restrict__ Qb, int hsel) {
    __shared__ __align__(16) char sraw[20480];
    pdl_sync();
    int b = blockIdx.x;
    if (b < 128) {
        body_proj4(b * 4, Pw0, Pb0, hsel, sraw);
    } else {
        int qb = b - 128;
        int l = qb / 100;
        int a0 = (qb % 100) * 2;
        body_qproj2(a0, l, Qw, Qb, hsel, sraw);
    }
}

__global__ void __launch_bounds__(256, 4)
logits_scores(const float* __restrict__ Pw1, const float* __restrict__ Pb1,
              float* __restrict__ out, int s,
              const float* __restrict__ Vw, const float* __restrict__ Vb) {
    __shared__ __align__(16) char sraw[20480];
    pdl_sync();
    int b = blockIdx.x;
    if (b < 250) {
        body_logits4(b * 4, Pw1, Pb1, out, s, sraw);
    } else {
        int sb = b - 250;
        int l = sb >> 8;
        int rr = sb & 255;
        body_scores(rr >> 1, l, rr & 1, Vw, Vb);
    }
}

__global__ void __launch_bounds__(256, 4)
qproj_k(const float* __restrict__ Qw, const float* __restrict__ Qb, int hsel) {
    __shared__ __align__(16) char sraw[10240];
    pdl_sync();
    int qb = blockIdx.x;
    int l = qb / 100;
    int a0 = (qb % 100) * 2;
    body_qproj2(a0, l, Qw, Qb, hsel, sraw);
}

__global__ void __launch_bounds__(256, 4)
scores_k(const float* __restrict__ Vw, const float* __restrict__ Vb) {
    pdl_sync();
    int sb = blockIdx.x;
    int l = sb >> 8;
    int rr = sb & 255;
    body_scores(rr >> 1, l, rr & 1, Vw, Vb);
}

__global__ void __launch_bounds__(256, 6)
context_v3(const float* __restrict__ embW,
           const int* __restrict__ targets, int s) {
    __shared__ float w[LT];
    __shared__ float red[8];
    pdl_sync();
    int n = blockIdx.x;
    int tid = threadIdx.x;
    int lane = tid & 31;

    float sc = g_scores[n * LT + tid];
    float m = sc;
    #pragma unroll
    for (int o = 16; o > 0; o >>= 1)
        m = fmaxf(m, __shfl_xor_sync(0xFFFFFFFFu, m, o));
    if (lane == 0) red[tid >> 5] = m;
    __syncthreads();
    if (tid < 8) {
        float v = red[tid];
        #pragma unroll
        for (int o = 4; o > 0; o >>= 1)
            v = fmaxf(v, __shfl_xor_sync(0xFFu, v, o, 8));
        if (tid == 0) red[0] = v;
    }
    __syncthreads();
    float mx = red[0];
    float e = __expf(sc - mx);
    float su = e;
    #pragma unroll
    for (int o = 16; o > 0; o >>= 1)
        su += __shfl_xor_sync(0xFFFFFFFFu, su, o);
    __syncthreads();
    if (lane == 0) red[tid >> 5] = su;
    __syncthreads();
    if (tid < 8) {
        float v = red[tid];
        #pragma unroll
        for (int o = 4; o > 0; o >>= 1)
            v += __shfl_xor_sync(0xFFu, v, o, 8);
        if (tid == 0) red[0] = v;
    }
    __syncthreads();
    w[tid] = e * (1.0f / red[0]);
    __syncthreads();

    const __half2* ep = reinterpret_cast<const __half2*>(g_eoH + (size_t)n * H) + tid;
    float ax = 0.f, ay = 0.f;
    #pragma unroll 16
    for (int lt = 0; lt < LT; lt++) {
        float2 f = __half22float2(ep[(size_t)lt * (NB * H / 2)]);
        float wv = w[lt];
        ax = fmaf(wv, f.x, ax);
        ay = fmaf(wv, f.y, ay);
    }
    g_xH[(E + 2 * tid + 0) * NB + n] = __float2half(ax);
    g_xH[(E + 2 * tid + 1) * NB + n] = __float2half(ay);

    int tok = (s == 0) ? 1 : targets[n * S + (s - 1)];
    g_xH[tid * NB + n] = __float2half(fmaxf(embW[(size_t)tok * E + tid], 0.0f));
}

// GRU: block = 2 j rows. grid 256. fp16 operands.
template <int KIN>
__global__ void __launch_bounds__(256, 2)
gru_row2(const float* __restrict__ Wih, const float* __restrict__ Whh,
         const float* __restrict__ bih, const float* __restrict__ bhh,
         int cur, int layer) {
    __shared__ float sw[8][2][6][16];
    __shared__ float sacc[2][4][16][64];
    __shared__ float sgate[2][4][64];
    pdl_sync();
    const int j0 = blockIdx.x * 2;
    const int tid = threadIdx.x;
    const int w = tid >> 5, lane = tid & 31;
    const int half = lane >> 4, ln = lane & 15;
    const int n0 = ln * 4;
    const int nxt = cur ^ 1;

    const __half* __restrict__ xin = (layer == 0) ? g_xH : g_hH[nxt][0];
    const __half* __restrict__ hin = g_hH[cur][layer];
    const float* __restrict__ hprev = g_h[cur][layer];
    float* __restrict__ hout = g_h[nxt][layer];
    __half* __restrict__ houtH = g_hH[nxt][layer];

    float aR[2][4] = {}, aZ[2][4] = {}, aI[2][4] = {}, aH[2][4] = {};

    // x part
    {
        const int kx = KIN / 8;
        const int kb = w * kx + half * (kx / 2);
        #pragma unroll
        for (int kc = 0; kc < kx / 2; kc += 16) {
            int k0 = kb + kc;
            #pragma unroll
            for (int g = 0; g < 6; g++) {
                int jj = g >= 3 ? 1 : 0;
                int gate = g - jj * 3;
                sw[w][half][g][ln] = Wih[((size_t)gate * H + j0 + jj) * KIN + k0 + ln];
            }
            __syncwarp();
            #pragma unroll
            for (int c = 0; c < 16; c++) {
                float4 xv = ld_half4(&xin[(k0 + c) * NB + n0]);
                #pragma unroll
                for (int jj = 0; jj < 2; jj++) {
                    float wR = sw[w][half][jj * 3 + 0][c];
                    float wZ = sw[w][half][jj * 3 + 1][c];
                    float wN = sw[w][half][jj * 3 + 2][c];
                    aR[jj][0]=fmaf(wR,xv.x,aR[jj][0]); aR[jj][1]=fmaf(wR,xv.y,aR[jj][1]);
                    aR[jj][2]=fmaf(wR,xv.z,aR[jj][2]); aR[jj][3]=fmaf(wR,xv.w,aR[jj][3]);
                    aZ[jj][0]=fmaf(wZ,xv.x,aZ[jj][0]); aZ[jj][1]=fmaf(wZ,xv.y,aZ[jj][1]);
                    aZ[jj][2]=fmaf(wZ,xv.z,aZ[jj][2]); aZ[jj][3]=fmaf(wZ,xv.w,aZ[jj][3]);
                    aI[jj][0]=fmaf(wN,xv.x,aI[jj][0]); aI[jj][1]=fmaf(wN,xv.y,aI[jj][1]);
                    aI[jj][2]=fmaf(wN,xv.z,aI[jj][2]); aI[jj][3]=fmaf(wN,xv.w,aI[jj][3]);
                }
            }
            __syncwarp();
        }
    }
    // h part
    {
        const int kb = w * 64 + half * 32;
        #pragma unroll
        for (int kc = 0; kc < 32; kc += 16) {
            int k0 = kb + kc;
            #pragma unroll
            for (int g = 0; g < 6; g++) {
                int jj = g >= 3 ? 1 : 0;
                int gate = g - jj * 3;
                sw[w][half][g][ln] = Whh[((size_t)gate * H + j0 + jj) * H + k0 + ln];
            }
            __syncwarp();
            #pragma unroll
            for (int c = 0; c < 16; c++) {
                float4 xv = ld_half4(&hin[(k0 + c) * NB + n0]);
                #pragma unroll
                for (int jj = 0; jj < 2; jj++) {
                    float wR = sw[w][half][jj * 3 + 0][c];
                    float wZ = sw[w][half][jj * 3 + 1][c];
                    float wN = sw[w][half][jj * 3 + 2][c];
                    aR[jj][0]=fmaf(wR,xv.x,aR[jj][0]); aR[jj][1]=fmaf(wR,xv.y,aR[jj][1]);
                    aR[jj][2]=fmaf(wR,xv.z,aR[jj][2]); aR[jj][3]=fmaf(wR,xv.w,aR[jj][3]);
                    aZ[jj][0]=fmaf(wZ,xv.x,aZ[jj][0]); aZ[jj][1]=fmaf(wZ,xv.y,aZ[jj][1]);
                    aZ[jj][2]=fmaf(wZ,xv.z,aZ[jj][2]); aZ[jj][3]=fmaf(wZ,xv.w,aZ[jj][3]);
                    aH[jj][0]=fmaf(wN,xv.x,aH[jj][0]); aH[jj][1]=fmaf(wN,xv.y,aH[jj][1]);
                    aH[jj][2]=fmaf(wN,xv.z,aH[jj][2]); aH[jj][3]=fmaf(wN,xv.w,aH[jj][3]);
                }
            }
            __syncwarp();
        }
    }
    const int ws = w * 2 + half;
    #pragma unroll
    for (int jj = 0; jj < 2; jj++) {
        *(float4*)&sacc[jj][0][ws][n0] = make_float4(aR[jj][0], aR[jj][1], aR[jj][2], aR[jj][3]);
        *(float4*)&sacc[jj][1][ws][n0] = make_float4(aZ[jj][0], aZ[jj][1], aZ[jj][2], aZ[jj][3]);
        *(float4*)&sacc[jj][2][ws][n0] = make_float4(aI[jj][0], aI[jj][1], aI[jj][2], aI[jj][3]);
        *(float4*)&sacc[jj][3][ws][n0] = make_float4(aH[jj][0], aH[jj][1], aH[jj][2], aH[jj][3]);
    }
    __syncthreads();
    #pragma unroll
    for (int i = 0; i < 2; i++) {
        int idx = tid + 256 * i;          // 0..511
        int jj = idx >> 8;
        int g  = (idx >> 6) & 3;
        int n  = idx & 63;
        float ssum = 0.f;
        #pragma unroll
        for (int ws2 = 0; ws2 < 16; ws2++) ssum += sacc[jj][g][ws2][n];
        sgate[jj][g][n] = ssum;
    }
    __syncthreads();
    if (tid < 128) {
        int jj = tid >> 6, n = tid & 63;
        int j = j0 + jj;
        float r = sigmoid_fast(sgate[jj][0][n] + bih[j] + bhh[j]);
        float z = sigmoid_fast(sgate[jj][1][n] + bih[H + j] + bhh[H + j]);
        float nn = tanh_fast(sgate[jj][2][n] + bih[2 * H + j] +
                             r * (sgate[jj][3][n] + bhh[2 * H + j]));
        float hp = hprev[j * NB + n];
        float hv = fmaf(z, hp - nn, nn);
        hout[j * NB + n] = hv;
        houtH[j * NB + n] = __float2half(hv);
    }
}

__global__ void __launch_bounds__(256, 4)
proj_k(const float* __restrict__ Pw0, const float* __restrict__ Pb0, int hsel) {
    __shared__ __align__(16) char sraw[20480];
    pdl_sync();
    body_proj4(blockIdx.x * 4, Pw0, Pb0, hsel, sraw);
}

__global__ void __launch_bounds__(256, 4)
logits_k(const float* __restrict__ Pw1, const float* __restrict__ Pb1,
         float* __restrict__ out, int s) {
    __shared__ __align__(16) char sraw[20480];
    pdl_sync();
    body_logits4(blockIdx.x * 4, Pw1, Pb1, out, s, sraw);
}

// ---------------- PDL launch helper ----------------
template <typename F, typename... Args>
static inline void pdl_launch(F kernel, dim3 grid, dim3 block, Args... args) {
    cudaLaunchConfig_t cfg;
    memset(&cfg, 0, sizeof(cfg));
    cfg.gridDim = grid;
    cfg.blockDim = block;
    cfg.dynamicSmemBytes = 0;
    cfg.stream = 0;
    cudaLaunchAttribute attr;
    attr.id = cudaLaunchAttributeProgrammaticStreamSerialization;
    attr.val.programmaticStreamSerializationAllowed = 1;
    cfg.attrs = &attr;
    cfg.numAttrs = 1;
    cudaLaunchKernelEx(&cfg, kernel, args...);
}

// ---------------- launcher ----------------
extern "C" void kernel_launch(void* const* d_in, const int* in_sizes, int n_in,
                              void* d_out, int out_size) {
    const float* eo      = (const float*)d_in[0];
    const float* efs     = (const float*)d_in[1];
    const int*   targets = (const int*)  d_in[2];
    const float* embW    = (const float*)d_in[3];
    const float* Qw      = (const float*)d_in[4];
    const float* Qb      = (const float*)d_in[5];
    const float* Kw      = (const float*)d_in[6];
    const float* Kb      = (const float*)d_in[7];
    const float* Vw      = (const float*)d_in[8];
    const float* Vb      = (const float*)d_in[9];
    const float* Wih0    = (const float*)d_in[10];
    const float* Whh0    = (const float*)d_in[11];
    const float* bih0    = (const float*)d_in[12];
    const float* bhh0    = (const float*)d_in[13];
    const float* Wih1    = (const float*)d_in[14];
    const float* Whh1    = (const float*)d_in[15];
    const float* bih1    = (const float*)d_in[16];
    const float* bhh1    = (const float*)d_in[17];
    const float* Pw0     = (const float*)d_in[18];
    const float* Pb0     = (const float*)d_in[19];
    const float* Pw1     = (const float*)d_in[20];
    const float* Pb1     = (const float*)d_in[21];
    float* out = (float*)d_out;

    prep_hinit<<<(L * NB * H + 255) / 256, 256>>>(efs);
    eo_to_half<<<(L * T * NB * H / 2 + 255) / 256, 256>>>(eo);
    kproj_gemm<<<dim3(128, 4, 2), 256>>>(eo, Kw, Kb);

    // prologue: attention inputs for step 0 (h slot 0)
    pdl_launch(qproj_k, dim3(200), dim3(256), Qw, Qb, 0);
    pdl_launch(scores_k, dim3(512), dim3(256), Vw, Vb);
    pdl_launch(context_v3, dim3(NB), dim3(256), embW, targets, 0);

    for (int s = 0; s < S; s++) {
        int cur = s & 1;
        int nxt = cur ^ 1;
        pdl_launch(gru_row2<E + H>, dim3(H / 2), dim3(256), Wih0, Whh0, bih0, bhh0, cur, 0);
        pdl_launch(gru_row2<H>, dim3(H / 2), dim3(256), Wih1, Whh1, bih1, bhh1, cur, 1);
        if (s < S - 1) {
            pdl_launch(proj_qproj, dim3(328), dim3(256), Pw0, Pb0, Qw, Qb, nxt);
            pdl_launch(logits_scores, dim3(762), dim3(256), Pw1, Pb1, out, s, Vw, Vb);
            pdl_launch(context_v3, dim3(NB), dim3(256), embW, targets, s + 1);
        } else {
            pdl_launch(proj_k, dim3(H / 4), dim3(256), Pw0, Pb0, nxt);
            pdl_launch(logits_k, dim3(V / 4), dim3(256), Pw1, Pb1, out, s);
        }
    }
}